// round 1
// baseline (speedup 1.0000x reference)
#include <cuda_runtime.h>
#include <cuda_bf16.h>
#include <math.h>

// Problem constants (match reference)
#define N_NODES 50000
#define N_EDGES 500000
#define IN_C    128
#define HID_C   256
#define OUT_C   64
// feats = x * (1 - 0.5); y = (sum_{i=0..5} A^i feats) / 6

// ---------------- scratch (static device globals; no allocation) ------------
__device__ int   g_cnt[N_NODES];
__device__ int   g_rp [N_NODES + 1];
__device__ int   g_wp [N_NODES];
__device__ int   g_col[N_EDGES];
__device__ float g_bufA[(size_t)N_NODES * IN_C];
__device__ float g_bufB[(size_t)N_NODES * IN_C];
__device__ float g_y   [(size_t)N_NODES * IN_C];
__device__ float g_h1  [(size_t)N_NODES * HID_C];
__device__ float g_h2  [(size_t)N_NODES * HID_C];

// ---------------- CSR build -------------------------------------------------
__global__ void zero_cnt_kernel() {
    int i = blockIdx.x * blockDim.x + threadIdx.x;
    if (i < N_NODES) g_cnt[i] = 0;
}

__global__ void hist_kernel(const int* __restrict__ ei) {
    int e = blockIdx.x * blockDim.x + threadIdx.x;
    if (e < N_EDGES) {
        int s = ei[e];           // src row
        atomicAdd(&g_cnt[s], 1);
    }
}

// Single-block exclusive scan over g_cnt -> g_rp (size N+1) and g_wp (=rp[i])
__global__ void scan_kernel() {
    __shared__ int s[1024];
    __shared__ int run_s;
    int t = threadIdx.x;
    if (t == 0) { run_s = 0; g_rp[0] = 0; }
    __syncthreads();
    for (int base = 0; base < N_NODES; base += 1024) {
        int i = base + t;
        int v = (i < N_NODES) ? g_cnt[i] : 0;
        s[t] = v;
        __syncthreads();
        // Hillis-Steele inclusive scan
        for (int off = 1; off < 1024; off <<= 1) {
            int x = (t >= off) ? s[t - off] : 0;
            __syncthreads();
            s[t] += x;
            __syncthreads();
        }
        int incl = s[t];
        int run = run_s;
        if (i < N_NODES) {
            g_rp[i + 1] = run + incl;
            g_wp[i]     = run + incl - v;  // exclusive
        }
        __syncthreads();
        if (t == 1023) run_s = run + s[1023];
        __syncthreads();
    }
}

__global__ void fill_kernel(const int* __restrict__ ei) {
    int e = blockIdx.x * blockDim.x + threadIdx.x;
    if (e < N_EDGES) {
        int s = ei[e];
        int d = ei[N_EDGES + e];
        int p = atomicAdd(&g_wp[s], 1);
        g_col[p] = d;
    }
}

// ---------------- propagation ----------------------------------------------
// feats = x*0.5 ; bufA = feats ; y = feats
__global__ void init_kernel(const float* __restrict__ x) {
    size_t i = (size_t)blockIdx.x * blockDim.x + threadIdx.x;
    size_t n4 = (size_t)N_NODES * IN_C / 4;
    if (i < n4) {
        float4 v = ((const float4*)x)[i];
        v.x *= 0.5f; v.y *= 0.5f; v.z *= 0.5f; v.w *= 0.5f;
        ((float4*)g_bufA)[i] = v;
        ((float4*)g_y)[i]    = v;
    }
}

// warp per row: hout[r] = sum_{j in adj(r)} hin[j]; y[r] += hout[r]
__global__ void spmm_kernel(const float* __restrict__ hin, float* __restrict__ hout) {
    int warp = (blockIdx.x * blockDim.x + threadIdx.x) >> 5;
    int lane = threadIdx.x & 31;
    if (warp >= N_NODES) return;
    int s = g_rp[warp];
    int e = g_rp[warp + 1];
    float4 acc = make_float4(0.f, 0.f, 0.f, 0.f);
    int idx = s;
    // unroll by 2 for a little more MLP
    for (; idx + 1 < e; idx += 2) {
        int j0 = g_col[idx];
        int j1 = g_col[idx + 1];
        float4 v0 = *(const float4*)(hin + (size_t)j0 * IN_C + lane * 4);
        float4 v1 = *(const float4*)(hin + (size_t)j1 * IN_C + lane * 4);
        acc.x += v0.x + v1.x; acc.y += v0.y + v1.y;
        acc.z += v0.z + v1.z; acc.w += v0.w + v1.w;
    }
    if (idx < e) {
        int j = g_col[idx];
        float4 v = *(const float4*)(hin + (size_t)j * IN_C + lane * 4);
        acc.x += v.x; acc.y += v.y; acc.z += v.z; acc.w += v.w;
    }
    *(float4*)(hout + (size_t)warp * IN_C + lane * 4) = acc;
    float4* yp = (float4*)(g_y + (size_t)warp * IN_C + lane * 4);
    float4 yv = *yp;
    yv.x += acc.x; yv.y += acc.y; yv.z += acc.z; yv.w += acc.w;
    *yp = yv;
}

// ---------------- fp32 tiled SGEMM  C[M,N] = relu(alpha*A[M,K] @ W[K,N] + b)
template <bool RELU>
__global__ void sgemm_kernel(const float* __restrict__ A, const float* __restrict__ W,
                             const float* __restrict__ bias, float* __restrict__ C,
                             int M, int N, int K, float alpha) {
    constexpr int BM = 128, BN = 64, BK = 16;
    __shared__ float As[BK][BM];
    __shared__ float Bs[BK][BN];
    const int m0 = blockIdx.x * BM;
    const int n0 = blockIdx.y * BN;
    const int t   = threadIdx.x;          // 0..255
    const int ty  = t >> 4;               // 0..15  (row group, TM=8)
    const int txx = t & 15;               // 0..15  (col group, TN=4)

    float acc[8][4];
#pragma unroll
    for (int i = 0; i < 8; ++i)
#pragma unroll
        for (int j = 0; j < 4; ++j) acc[i][j] = 0.f;

    for (int k0 = 0; k0 < K; k0 += BK) {
        // A tile: 128x16 = 512 float4 loads, 2 per thread, stored transposed
#pragma unroll
        for (int l = 0; l < 2; ++l) {
            int f  = t + l * 256;
            int ar = f >> 2;
            int ac = (f & 3) * 4;
            int m  = m0 + ar;
            float4 v = make_float4(0.f, 0.f, 0.f, 0.f);
            if (m < M) v = *(const float4*)(A + (size_t)m * K + k0 + ac);
            As[ac + 0][ar] = v.x * alpha;
            As[ac + 1][ar] = v.y * alpha;
            As[ac + 2][ar] = v.z * alpha;
            As[ac + 3][ar] = v.w * alpha;
        }
        // B tile: 16x64 = 256 float4 loads, 1 per thread
        {
            int br = t >> 4;
            int bc = (t & 15) * 4;
            *(float4*)&Bs[br][bc] = *(const float4*)(W + (size_t)(k0 + br) * N + n0 + bc);
        }
        __syncthreads();
#pragma unroll
        for (int kk = 0; kk < BK; ++kk) {
            float4 b4 = *(const float4*)&Bs[kk][txx * 4];
            float a[8];
#pragma unroll
            for (int i = 0; i < 8; ++i) a[i] = As[kk][ty * 8 + i];
#pragma unroll
            for (int i = 0; i < 8; ++i) {
                acc[i][0] += a[i] * b4.x;
                acc[i][1] += a[i] * b4.y;
                acc[i][2] += a[i] * b4.z;
                acc[i][3] += a[i] * b4.w;
            }
        }
        __syncthreads();
    }

    float4 bb = *(const float4*)(bias + n0 + txx * 4);
#pragma unroll
    for (int i = 0; i < 8; ++i) {
        int m = m0 + ty * 8 + i;
        if (m < M) {
            float4 r;
            r.x = acc[i][0] + bb.x;
            r.y = acc[i][1] + bb.y;
            r.z = acc[i][2] + bb.z;
            r.w = acc[i][3] + bb.w;
            if (RELU) {
                r.x = fmaxf(r.x, 0.f); r.y = fmaxf(r.y, 0.f);
                r.z = fmaxf(r.z, 0.f); r.w = fmaxf(r.w, 0.f);
            }
            *(float4*)(C + (size_t)m * N + n0 + txx * 4) = r;
        }
    }
}

// ---------------- log-softmax over 64 cols, warp per row, in place ----------
__global__ void lsm_kernel(float* __restrict__ out) {
    int warp = (blockIdx.x * blockDim.x + threadIdx.x) >> 5;
    int lane = threadIdx.x & 31;
    if (warp >= N_NODES) return;
    float* row = out + (size_t)warp * OUT_C;
    float v0 = row[lane];
    float v1 = row[lane + 32];
    float m = fmaxf(v0, v1);
#pragma unroll
    for (int off = 16; off > 0; off >>= 1)
        m = fmaxf(m, __shfl_xor_sync(0xFFFFFFFFu, m, off));
    float s = expf(v0 - m) + expf(v1 - m);
#pragma unroll
    for (int off = 16; off > 0; off >>= 1)
        s += __shfl_xor_sync(0xFFFFFFFFu, s, off);
    float l = m + logf(s);
    row[lane]      = v0 - l;
    row[lane + 32] = v1 - l;
}

// ---------------- launch ----------------------------------------------------
extern "C" void kernel_launch(void* const* d_in, const int* in_sizes, int n_in,
                              void* d_out, int out_size) {
    const float* x  = (const float*)d_in[0];
    const int*   ei = (const int*)  d_in[1];   // [2, N_EDGES] int32
    const float* W1 = (const float*)d_in[2];
    const float* b1 = (const float*)d_in[3];
    const float* W2 = (const float*)d_in[4];
    const float* b2 = (const float*)d_in[5];
    const float* W3 = (const float*)d_in[6];
    const float* b3 = (const float*)d_in[7];
    float* out = (float*)d_out;

    (void)in_sizes; (void)n_in; (void)out_size;

    void *pA, *pB, *pY, *pH1, *pH2;
    cudaGetSymbolAddress(&pA,  g_bufA);
    cudaGetSymbolAddress(&pB,  g_bufB);
    cudaGetSymbolAddress(&pY,  g_y);
    cudaGetSymbolAddress(&pH1, g_h1);
    cudaGetSymbolAddress(&pH2, g_h2);
    float* bufA = (float*)pA;
    float* bufB = (float*)pB;
    float* ybuf = (float*)pY;
    float* h1   = (float*)pH1;
    float* h2   = (float*)pH2;

    // 1) CSR build
    zero_cnt_kernel<<<(N_NODES + 255) / 256, 256>>>();
    hist_kernel<<<(N_EDGES + 255) / 256, 256>>>(ei);
    scan_kernel<<<1, 1024>>>();
    fill_kernel<<<(N_EDGES + 255) / 256, 256>>>(ei);

    // 2) init feats & y
    {
        size_t n4 = (size_t)N_NODES * IN_C / 4;
        init_kernel<<<(int)((n4 + 255) / 256), 256>>>(x);
    }

    // 3) 5x SpMM, ping-pong buffers; y accumulates
    const int spmm_blocks = (N_NODES * 32 + 255) / 256;
    spmm_kernel<<<spmm_blocks, 256>>>(bufA, bufB);
    spmm_kernel<<<spmm_blocks, 256>>>(bufB, bufA);
    spmm_kernel<<<spmm_blocks, 256>>>(bufA, bufB);
    spmm_kernel<<<spmm_blocks, 256>>>(bufB, bufA);
    spmm_kernel<<<spmm_blocks, 256>>>(bufA, bufB);

    // 4) MLP  (1/6 folded into GEMM1's alpha)
    {
        dim3 g1((N_NODES + 127) / 128, HID_C / 64);
        sgemm_kernel<true><<<g1, 256>>>(ybuf, W1, b1, h1, N_NODES, HID_C, IN_C, 1.0f / 6.0f);
        dim3 g2((N_NODES + 127) / 128, HID_C / 64);
        sgemm_kernel<true><<<g2, 256>>>(h1, W2, b2, h2, N_NODES, HID_C, HID_C, 1.0f);
        dim3 g3((N_NODES + 127) / 128, OUT_C / 64);
        sgemm_kernel<false><<<g3, 256>>>(h2, W3, b3, out, N_NODES, OUT_C, HID_C, 1.0f);
    }

    // 5) log-softmax in place on d_out
    lsm_kernel<<<(N_NODES * 32 + 255) / 256, 256>>>(out);
}

// round 3
// speedup vs baseline: 1.2088x; 1.2088x over previous
#include <cuda_runtime.h>
#include <cuda_bf16.h>
#include <math.h>
#include <stdint.h>

#define N_NODES 50000
#define N_EDGES 500000
#define IN_C    128
#define HID_C   256
#define OUT_C   64

// ===================== scratch (static device globals) ======================
__device__ int   g_cnt[N_NODES];
__device__ int   g_rp [N_NODES + 1];
__device__ int   g_wp [N_NODES];
__device__ int   g_col[N_EDGES];
__device__ float g_bufA[(size_t)N_NODES * IN_C];
__device__ float g_bufB[(size_t)N_NODES * IN_C];
__device__ float g_y   [(size_t)N_NODES * IN_C];
// bf16 2-term-split GEMM operands: A' = [hi | lo | hi], W'^T = [hi | hi | lo]
__device__ __nv_bfloat16 g_a3y [(size_t)N_NODES * (3 * IN_C)];   // 50000 x 384
__device__ __nv_bfloat16 g_h13 [(size_t)N_NODES * (3 * HID_C)];  // 50000 x 768
__device__ __nv_bfloat16 g_h23 [(size_t)N_NODES * (3 * HID_C)];  // 50000 x 768
__device__ __nv_bfloat16 g_wt1 [(size_t)HID_C * (3 * IN_C)];     // 256 x 384  (N-major)
__device__ __nv_bfloat16 g_wt2 [(size_t)HID_C * (3 * HID_C)];    // 256 x 768
__device__ __nv_bfloat16 g_wt3 [(size_t)OUT_C * (3 * HID_C)];    // 64  x 768

// ===================== small helpers ========================================
__device__ __forceinline__ uint32_t smem_u32(const void* p) {
    uint32_t a;
    asm("{ .reg .u64 t; cvta.to.shared.u64 t, %1; cvt.u32.u64 %0, t; }" : "=r"(a) : "l"(p));
    return a;
}
__device__ __forceinline__ uint32_t pack_hi2(float a, float b, float& la, float& lb) {
    __nv_bfloat16 ah = __float2bfloat16(a);
    __nv_bfloat16 bh = __float2bfloat16(b);
    la = a - __bfloat162float(ah);
    lb = b - __bfloat162float(bh);
    __nv_bfloat162 h2; h2.x = ah; h2.y = bh;
    return *(uint32_t*)&h2;
}
__device__ __forceinline__ uint32_t pack_bf2(float a, float b) {
    __nv_bfloat162 h2; h2.x = __float2bfloat16(a); h2.y = __float2bfloat16(b);
    return *(uint32_t*)&h2;
}

__device__ __forceinline__ void ldsm_x4(uint32_t (&r)[4], uint32_t addr) {
    asm volatile("ldmatrix.sync.aligned.m8n8.x4.shared.b16 {%0,%1,%2,%3},[%4];"
                 : "=r"(r[0]), "=r"(r[1]), "=r"(r[2]), "=r"(r[3]) : "r"(addr));
}
__device__ __forceinline__ void ldsm_x2(uint32_t (&r)[2], uint32_t addr) {
    asm volatile("ldmatrix.sync.aligned.m8n8.x2.shared.b16 {%0,%1},[%2];"
                 : "=r"(r[0]), "=r"(r[1]) : "r"(addr));
}
__device__ __forceinline__ void mma_bf16(float (&d)[4], const uint32_t (&a)[4],
                                         const uint32_t (&b)[2]) {
    asm volatile("mma.sync.aligned.m16n8k16.row.col.f32.bf16.bf16.f32 "
                 "{%0,%1,%2,%3},{%4,%5,%6,%7},{%8,%9},{%0,%1,%2,%3};"
                 : "+f"(d[0]), "+f"(d[1]), "+f"(d[2]), "+f"(d[3])
                 : "r"(a[0]), "r"(a[1]), "r"(a[2]), "r"(a[3]), "r"(b[0]), "r"(b[1]));
}
__device__ __forceinline__ void cp16(uint32_t dst, const void* src, int sz) {
    asm volatile("cp.async.cg.shared.global [%0],[%1],16,%2;"
                 :: "r"(dst), "l"(src), "r"(sz) : "memory");
}
__device__ __forceinline__ void cp16(uint32_t dst, const void* src) {
    asm volatile("cp.async.cg.shared.global [%0],[%1],16;"
                 :: "r"(dst), "l"(src) : "memory");
}
#define CP_COMMIT() asm volatile("cp.async.commit_group;" ::: "memory")
#define CP_WAIT0()  asm volatile("cp.async.wait_group 0;" ::: "memory")

// ===================== CSR build ============================================
__global__ void zero_cnt_kernel() {
    int i = blockIdx.x * blockDim.x + threadIdx.x;
    if (i < N_NODES) g_cnt[i] = 0;
}
__global__ void hist_kernel(const int* __restrict__ ei) {
    int e = blockIdx.x * blockDim.x + threadIdx.x;
    if (e < N_EDGES) atomicAdd(&g_cnt[ei[e]], 1);
}
__global__ void scan_kernel() {
    __shared__ int s[1024];
    __shared__ int run_s;
    int t = threadIdx.x;
    if (t == 0) { run_s = 0; g_rp[0] = 0; }
    __syncthreads();
    for (int base = 0; base < N_NODES; base += 1024) {
        int i = base + t;
        int v = (i < N_NODES) ? g_cnt[i] : 0;
        s[t] = v;
        __syncthreads();
        for (int off = 1; off < 1024; off <<= 1) {
            int x = (t >= off) ? s[t - off] : 0;
            __syncthreads();
            s[t] += x;
            __syncthreads();
        }
        int incl = s[t];
        int run = run_s;
        if (i < N_NODES) {
            g_rp[i + 1] = run + incl;
            g_wp[i]     = run + incl - v;
        }
        __syncthreads();
        if (t == 1023) run_s = run + s[1023];
        __syncthreads();
    }
}
__global__ void fill_kernel(const int* __restrict__ ei) {
    int e = blockIdx.x * blockDim.x + threadIdx.x;
    if (e < N_EDGES) {
        int s = ei[e];
        int d = ei[N_EDGES + e];
        int p = atomicAdd(&g_wp[s], 1);
        g_col[p] = d;
    }
}

// ===================== propagation ==========================================
__global__ void init_kernel(const float* __restrict__ x) {
    size_t i = (size_t)blockIdx.x * blockDim.x + threadIdx.x;
    size_t n4 = (size_t)N_NODES * IN_C / 4;
    if (i < n4) {
        float4 v = ((const float4*)x)[i];
        v.x *= 0.5f; v.y *= 0.5f; v.z *= 0.5f; v.w *= 0.5f;
        ((float4*)g_bufA)[i] = v;
        ((float4*)g_y)[i]    = v;
    }
}

// warp per row gather; last hop emits bf16-split A' of y/6 directly
template <bool EMIT>
__global__ void spmm_kernel(const float* __restrict__ hin, float* __restrict__ hout) {
    int warp = (blockIdx.x * blockDim.x + threadIdx.x) >> 5;
    int lane = threadIdx.x & 31;
    if (warp >= N_NODES) return;
    int s = g_rp[warp];
    int e = g_rp[warp + 1];
    float4 acc = make_float4(0.f, 0.f, 0.f, 0.f);
    int idx = s;
    for (; idx + 1 < e; idx += 2) {
        int j0 = g_col[idx];
        int j1 = g_col[idx + 1];
        float4 v0 = *(const float4*)(hin + (size_t)j0 * IN_C + lane * 4);
        float4 v1 = *(const float4*)(hin + (size_t)j1 * IN_C + lane * 4);
        acc.x += v0.x + v1.x; acc.y += v0.y + v1.y;
        acc.z += v0.z + v1.z; acc.w += v0.w + v1.w;
    }
    if (idx < e) {
        int j = g_col[idx];
        float4 v = *(const float4*)(hin + (size_t)j * IN_C + lane * 4);
        acc.x += v.x; acc.y += v.y; acc.z += v.z; acc.w += v.w;
    }
    float4* yp = (float4*)(g_y + (size_t)warp * IN_C + lane * 4);
    float4 yv = *yp;
    yv.x += acc.x; yv.y += acc.y; yv.z += acc.z; yv.w += acc.w;
    *yp = yv;
    if (!EMIT) {
        *(float4*)(hout + (size_t)warp * IN_C + lane * 4) = acc;
    } else {
        const float sc = 1.0f / 6.0f;
        float a = yv.x * sc, b = yv.y * sc, c = yv.z * sc, d = yv.w * sc;
        float la, lb, lc, ld;
        uint2 h2, l2;
        h2.x = pack_hi2(a, b, la, lb);
        h2.y = pack_hi2(c, d, lc, ld);
        l2.x = pack_bf2(la, lb);
        l2.y = pack_bf2(lc, ld);
        __nv_bfloat16* row = g_a3y + (size_t)warp * (3 * IN_C);
        int c0 = lane * 4;
        *(uint2*)(row + c0)            = h2;   // hi
        *(uint2*)(row + IN_C + c0)     = l2;   // lo
        *(uint2*)(row + 2 * IN_C + c0) = h2;   // hi (pairs with W lo)
    }
}

// W[K,N] fp32 -> Wt3[N, 3K] bf16 = [hi | hi | lo] along K3
__global__ void convw_kernel(const float* __restrict__ W, __nv_bfloat16* __restrict__ Wt3,
                             int K, int N) {
    int i = blockIdx.x * blockDim.x + threadIdx.x;
    if (i >= K * N) return;
    int k = i / N, n = i % N;
    float v = W[i];
    __nv_bfloat16 hi = __float2bfloat16(v);
    __nv_bfloat16 lo = __float2bfloat16(v - __bfloat162float(hi));
    size_t rb = (size_t)n * 3 * K;
    Wt3[rb + k]         = hi;
    Wt3[rb + K + k]     = hi;
    Wt3[rb + 2 * K + k] = lo;
}

// ===================== mma.sync GEMM (sm_100-base tensor path) ==============
// CTA tile 128x64, BK=32, 8 warps (4x2), warp tile 32x32, double buffer.
// A3 row-major [M, K3]; Bt3 [N, K3] (== col-major B for row.col mma).
// OUTMODE 0: relu(acc+bias) -> bf16 triple [hi|lo|hi] in outb (row width 768)
// OUTMODE 1: acc+bias (fp32) -> outf (row width 64)
template <int K3, int OUTMODE>
__global__ void __launch_bounds__(256) mgemm_kernel(
    const __nv_bfloat16* __restrict__ A3, const __nv_bfloat16* __restrict__ Bt3,
    const float* __restrict__ bias, float* __restrict__ outf,
    __nv_bfloat16* __restrict__ outb)
{
    constexpr int NK = K3 / 32;
    constexpr int AROWB = 80;                 // 32 bf16 + 8 pad, bytes
    constexpr int A_STRIDE = 128 * AROWB;     // 10240
    constexpr int B_STRIDE = 64 * AROWB;      // 5120

    __shared__ __align__(16) unsigned char smA[2 * A_STRIDE];
    __shared__ __align__(16) unsigned char smB[2 * B_STRIDE];
    __shared__ float sbias[64];

    const int t = threadIdx.x;
    const int lane = t & 31;
    const int wid = t >> 5;
    const int wm = wid & 3;        // 0..3 -> 32-row block
    const int wn = wid >> 2;       // 0..1 -> 32-col block
    const int m0 = blockIdx.x * 128;
    const int n0 = blockIdx.y * 64;

    const uint32_t smA_addr = smem_u32(smA);
    const uint32_t smB_addr = smem_u32(smB);

    if (t < 64) sbias[t] = bias[n0 + t];

    float acc[2][4][4];
#pragma unroll
    for (int mi = 0; mi < 2; ++mi)
#pragma unroll
        for (int ni = 0; ni < 4; ++ni)
#pragma unroll
            for (int q = 0; q < 4; ++q) acc[mi][ni][q] = 0.f;

    auto load_tile = [&](int kbase, int s) {
#pragma unroll
        for (int i = 0; i < 2; ++i) {
            int u = t + i * 256;
            int row = u >> 2, seg = u & 3;
            uint32_t dst = smA_addr + s * A_STRIDE + row * AROWB + seg * 16;
            int m = m0 + row;
            int mc = (m < N_NODES) ? m : 0;
            const __nv_bfloat16* src = A3 + (size_t)mc * K3 + kbase + seg * 8;
            cp16(dst, src, (m < N_NODES) ? 16 : 0);
        }
        {
            int row = t >> 2, seg = t & 3;
            uint32_t dst = smB_addr + s * B_STRIDE + row * AROWB + seg * 16;
            const __nv_bfloat16* src = Bt3 + (size_t)(n0 + row) * K3 + kbase + seg * 8;
            cp16(dst, src);
        }
    };

    load_tile(0, 0);
    CP_COMMIT();
    CP_WAIT0();
    __syncthreads();

    for (int kt = 0; kt < NK; ++kt) {
        const int s = kt & 1;
        if (kt + 1 < NK) { load_tile((kt + 1) * 32, s ^ 1); CP_COMMIT(); }

        const uint32_t abase0 = smA_addr + s * A_STRIDE +
                                (wm * 32 + (lane & 15)) * AROWB + ((lane >> 4) * 16);
        const uint32_t bbase0 = smB_addr + s * B_STRIDE +
                                (wn * 32 + (lane & 7)) * AROWB + (((lane >> 3) & 1) * 16);
#pragma unroll
        for (int h = 0; h < 2; ++h) {
            uint32_t aF[2][4];
            uint32_t bF[4][2];
            ldsm_x4(aF[0], abase0 + h * 32);
            ldsm_x4(aF[1], abase0 + h * 32 + 16 * AROWB);
#pragma unroll
            for (int ni = 0; ni < 4; ++ni)
                ldsm_x2(bF[ni], bbase0 + h * 32 + ni * 8 * AROWB);
#pragma unroll
            for (int mi = 0; mi < 2; ++mi)
#pragma unroll
                for (int ni = 0; ni < 4; ++ni)
                    mma_bf16(acc[mi][ni], aF[mi], bF[ni]);
        }

        if (kt + 1 < NK) { CP_WAIT0(); __syncthreads(); }
    }

    // ---------------- epilogue ----------------
    const int lr = lane >> 2;        // 0..7
    const int lc = (lane & 3) * 2;   // 0,2,4,6
#pragma unroll
    for (int mi = 0; mi < 2; ++mi) {
#pragma unroll
        for (int half = 0; half < 2; ++half) {
            const int m = m0 + wm * 32 + mi * 16 + lr + half * 8;
            if (m < N_NODES) {
                if (OUTMODE == 0) {
                    __nv_bfloat16* orow = outb + (size_t)m * 768;
#pragma unroll
                    for (int ni = 0; ni < 4; ++ni) {
                        int cl = wn * 32 + ni * 8 + lc;
                        float a = acc[mi][ni][half * 2 + 0] + sbias[cl];
                        float b = acc[mi][ni][half * 2 + 1] + sbias[cl + 1];
                        a = fmaxf(a, 0.f); b = fmaxf(b, 0.f);
                        float la, lb;
                        uint32_t hi = pack_hi2(a, b, la, lb);
                        uint32_t lo = pack_bf2(la, lb);
                        int col = n0 + cl;
                        *(uint32_t*)(orow + col)       = hi;
                        *(uint32_t*)(orow + 256 + col) = lo;
                        *(uint32_t*)(orow + 512 + col) = hi;
                    }
                } else {
#pragma unroll
                    for (int ni = 0; ni < 4; ++ni) {
                        int cl = wn * 32 + ni * 8 + lc;
                        float a = acc[mi][ni][half * 2 + 0] + sbias[cl];
                        float b = acc[mi][ni][half * 2 + 1] + sbias[cl + 1];
                        float2 v = make_float2(a, b);
                        *(float2*)(outf + (size_t)m * 64 + cl) = v;
                    }
                }
            }
        }
    }
}

// ---------------- log-softmax over 64 cols, warp per row, in place ----------
__global__ void lsm_kernel(float* __restrict__ out) {
    int warp = (blockIdx.x * blockDim.x + threadIdx.x) >> 5;
    int lane = threadIdx.x & 31;
    if (warp >= N_NODES) return;
    float* row = out + (size_t)warp * OUT_C;
    float v0 = row[lane];
    float v1 = row[lane + 32];
    float m = fmaxf(v0, v1);
#pragma unroll
    for (int off = 16; off > 0; off >>= 1)
        m = fmaxf(m, __shfl_xor_sync(0xFFFFFFFFu, m, off));
    float s = expf(v0 - m) + expf(v1 - m);
#pragma unroll
    for (int off = 16; off > 0; off >>= 1)
        s += __shfl_xor_sync(0xFFFFFFFFu, s, off);
    float l = m + logf(s);
    row[lane]      = v0 - l;
    row[lane + 32] = v1 - l;
}

// ===================== launch ===============================================
extern "C" void kernel_launch(void* const* d_in, const int* in_sizes, int n_in,
                              void* d_out, int out_size) {
    const float* x  = (const float*)d_in[0];
    const int*   ei = (const int*)  d_in[1];
    const float* W1 = (const float*)d_in[2];
    const float* b1 = (const float*)d_in[3];
    const float* W2 = (const float*)d_in[4];
    const float* b2 = (const float*)d_in[5];
    const float* W3 = (const float*)d_in[6];
    const float* b3 = (const float*)d_in[7];
    float* out = (float*)d_out;
    (void)in_sizes; (void)n_in; (void)out_size;

    void *pA, *pB, *pa3, *ph13, *ph23, *pw1, *pw2, *pw3;
    cudaGetSymbolAddress(&pA,  g_bufA);
    cudaGetSymbolAddress(&pB,  g_bufB);
    cudaGetSymbolAddress(&pa3, g_a3y);
    cudaGetSymbolAddress(&ph13, g_h13);
    cudaGetSymbolAddress(&ph23, g_h23);
    cudaGetSymbolAddress(&pw1, g_wt1);
    cudaGetSymbolAddress(&pw2, g_wt2);
    cudaGetSymbolAddress(&pw3, g_wt3);
    float* bufA = (float*)pA;
    float* bufB = (float*)pB;
    __nv_bfloat16* a3y = (__nv_bfloat16*)pa3;
    __nv_bfloat16* h13 = (__nv_bfloat16*)ph13;
    __nv_bfloat16* h23 = (__nv_bfloat16*)ph23;
    __nv_bfloat16* wt1 = (__nv_bfloat16*)pw1;
    __nv_bfloat16* wt2 = (__nv_bfloat16*)pw2;
    __nv_bfloat16* wt3 = (__nv_bfloat16*)pw3;

    // 1) CSR build
    zero_cnt_kernel<<<(N_NODES + 255) / 256, 256>>>();
    hist_kernel<<<(N_EDGES + 255) / 256, 256>>>(ei);
    scan_kernel<<<1, 1024>>>();
    fill_kernel<<<(N_EDGES + 255) / 256, 256>>>(ei);

    // 2) weight conversions (independent of CSR)
    convw_kernel<<<(IN_C * HID_C + 255) / 256, 256>>>(W1, wt1, IN_C, HID_C);
    convw_kernel<<<(HID_C * HID_C + 255) / 256, 256>>>(W2, wt2, HID_C, HID_C);
    convw_kernel<<<(HID_C * OUT_C + 255) / 256, 256>>>(W3, wt3, HID_C, OUT_C);

    // 3) init feats & y
    {
        size_t n4 = (size_t)N_NODES * IN_C / 4;
        init_kernel<<<(int)((n4 + 255) / 256), 256>>>(x);
    }

    // 4) 5x SpMM; last hop emits bf16-split A' of y/6
    const int spmm_blocks = (N_NODES * 32 + 255) / 256;
    spmm_kernel<false><<<spmm_blocks, 256>>>(bufA, bufB);
    spmm_kernel<false><<<spmm_blocks, 256>>>(bufB, bufA);
    spmm_kernel<false><<<spmm_blocks, 256>>>(bufA, bufB);
    spmm_kernel<false><<<spmm_blocks, 256>>>(bufB, bufA);
    spmm_kernel<true><<<spmm_blocks, 256>>>(bufA, bufB);

    // 5) MLP on tensor cores (bf16 3-term split), fused bias/relu/split emit
    const int mtiles = (N_NODES + 127) / 128;  // 391
    mgemm_kernel<384, 0><<<dim3(mtiles, HID_C / 64), 256>>>(a3y, wt1, b1, nullptr, h13);
    mgemm_kernel<768, 0><<<dim3(mtiles, HID_C / 64), 256>>>(h13, wt2, b2, nullptr, h23);
    mgemm_kernel<768, 1><<<dim3(mtiles, 1), 256>>>(h23, wt3, b3, out, nullptr);

    // 6) log-softmax in place on d_out
    lsm_kernel<<<(N_NODES * 32 + 255) / 256, 256>>>(out);
}

// round 4
// speedup vs baseline: 1.4618x; 1.2093x over previous
#include <cuda_runtime.h>
#include <cuda_bf16.h>
#include <math.h>
#include <stdint.h>

#define N_NODES 50000
#define N_EDGES 500000
#define IN_C    128
#define HID_C   256
#define OUT_C   64
#define SCAN_BLOCKS ((N_NODES + 255) / 256)   // 196

// ===================== scratch (static device globals) ======================
__device__ int   g_cnt[N_NODES];
__device__ int   g_rp [N_NODES + 1];
__device__ int   g_wp [N_NODES];
__device__ int   g_bsum[SCAN_BLOCKS];
__device__ int   g_boff[SCAN_BLOCKS];
__device__ int   g_col[N_EDGES];
__device__ float g_bufF[(size_t)N_NODES * IN_C];   // f = x * 0.5
__device__ float g_bufA[(size_t)N_NODES * IN_C];   // Horner ping
__device__ float g_bufB[(size_t)N_NODES * IN_C];   // Horner pong
// bf16 3-term-split GEMM operands: A' = [hi | lo | hi], W'^T = [hi | hi | lo]
__device__ __nv_bfloat16 g_a3y [(size_t)N_NODES * (3 * IN_C)];   // 50000 x 384
__device__ __nv_bfloat16 g_h13 [(size_t)N_NODES * (3 * HID_C)];  // 50000 x 768
__device__ __nv_bfloat16 g_h23 [(size_t)N_NODES * (3 * HID_C)];  // 50000 x 768
__device__ __nv_bfloat16 g_wt1 [(size_t)HID_C * (3 * IN_C)];
__device__ __nv_bfloat16 g_wt2 [(size_t)HID_C * (3 * HID_C)];
__device__ __nv_bfloat16 g_wt3 [(size_t)OUT_C * (3 * HID_C)];

// ===================== small helpers ========================================
__device__ __forceinline__ uint32_t smem_u32(const void* p) {
    uint32_t a;
    asm("{ .reg .u64 t; cvta.to.shared.u64 t, %1; cvt.u32.u64 %0, t; }" : "=r"(a) : "l"(p));
    return a;
}
__device__ __forceinline__ uint32_t pack_hi2(float a, float b, float& la, float& lb) {
    __nv_bfloat16 ah = __float2bfloat16(a);
    __nv_bfloat16 bh = __float2bfloat16(b);
    la = a - __bfloat162float(ah);
    lb = b - __bfloat162float(bh);
    __nv_bfloat162 h2; h2.x = ah; h2.y = bh;
    return *(uint32_t*)&h2;
}
__device__ __forceinline__ uint32_t pack_bf2(float a, float b) {
    __nv_bfloat162 h2; h2.x = __float2bfloat16(a); h2.y = __float2bfloat16(b);
    return *(uint32_t*)&h2;
}
__device__ __forceinline__ void ldsm_x4(uint32_t (&r)[4], uint32_t addr) {
    asm volatile("ldmatrix.sync.aligned.m8n8.x4.shared.b16 {%0,%1,%2,%3},[%4];"
                 : "=r"(r[0]), "=r"(r[1]), "=r"(r[2]), "=r"(r[3]) : "r"(addr));
}
__device__ __forceinline__ void ldsm_x2(uint32_t (&r)[2], uint32_t addr) {
    asm volatile("ldmatrix.sync.aligned.m8n8.x2.shared.b16 {%0,%1},[%2];"
                 : "=r"(r[0]), "=r"(r[1]) : "r"(addr));
}
__device__ __forceinline__ void mma_bf16(float (&d)[4], const uint32_t (&a)[4],
                                         const uint32_t (&b)[2]) {
    asm volatile("mma.sync.aligned.m16n8k16.row.col.f32.bf16.bf16.f32 "
                 "{%0,%1,%2,%3},{%4,%5,%6,%7},{%8,%9},{%0,%1,%2,%3};"
                 : "+f"(d[0]), "+f"(d[1]), "+f"(d[2]), "+f"(d[3])
                 : "r"(a[0]), "r"(a[1]), "r"(a[2]), "r"(a[3]), "r"(b[0]), "r"(b[1]));
}
__device__ __forceinline__ void cp16(uint32_t dst, const void* src, int sz) {
    asm volatile("cp.async.cg.shared.global [%0],[%1],16,%2;"
                 :: "r"(dst), "l"(src), "r"(sz) : "memory");
}
__device__ __forceinline__ void cp16(uint32_t dst, const void* src) {
    asm volatile("cp.async.cg.shared.global [%0],[%1],16;"
                 :: "r"(dst), "l"(src) : "memory");
}
#define CP_COMMIT() asm volatile("cp.async.commit_group;" ::: "memory")
#define CP_WAIT0()  asm volatile("cp.async.wait_group 0;" ::: "memory")

// ===================== CSR build ============================================
__global__ void zero_cnt_kernel() {
    int i = blockIdx.x * blockDim.x + threadIdx.x;
    if (i < N_NODES) g_cnt[i] = 0;
}
__global__ void hist_kernel(const int* __restrict__ ei) {
    int e = blockIdx.x * blockDim.x + threadIdx.x;
    if (e < N_EDGES) atomicAdd(&g_cnt[ei[e]], 1);
}
// two-level scan: s1 block-local inclusive + block sums
__global__ void scan1_kernel() {
    int b = blockIdx.x, t = threadIdx.x;
    int i = b * 256 + t;
    int lane = t & 31, w = t >> 5;
    int v = (i < N_NODES) ? g_cnt[i] : 0;
    int x = v;
#pragma unroll
    for (int o = 1; o < 32; o <<= 1) {
        int y = __shfl_up_sync(0xFFFFFFFFu, x, o);
        if (lane >= o) x += y;
    }
    __shared__ int ws[8];
    if (lane == 31) ws[w] = x;
    __syncthreads();
    if (w == 0 && lane < 8) {
        int y = ws[lane];
#pragma unroll
        for (int o = 1; o < 8; o <<= 1) {
            int z = __shfl_up_sync(0xFFu, y, o);
            if (lane >= o) y += z;
        }
        ws[lane] = y;
    }
    __syncthreads();
    int incl = x + (w > 0 ? ws[w - 1] : 0);
    if (i < N_NODES) g_rp[i + 1] = incl;
    if (t == 255) g_bsum[b] = incl;
}
__global__ void scan2_kernel() {
    int t = threadIdx.x;
    int lane = t & 31, w = t >> 5;
    int v = (t < SCAN_BLOCKS) ? g_bsum[t] : 0;
    int x = v;
#pragma unroll
    for (int o = 1; o < 32; o <<= 1) {
        int y = __shfl_up_sync(0xFFFFFFFFu, x, o);
        if (lane >= o) x += y;
    }
    __shared__ int ws[8];
    if (lane == 31) ws[w] = x;
    __syncthreads();
    if (w == 0 && lane < 8) {
        int y = ws[lane];
#pragma unroll
        for (int o = 1; o < 8; o <<= 1) {
            int z = __shfl_up_sync(0xFFu, y, o);
            if (lane >= o) y += z;
        }
        ws[lane] = y;
    }
    __syncthreads();
    int incl = x + (w > 0 ? ws[w - 1] : 0);
    if (t < SCAN_BLOCKS) g_boff[t] = incl - v;   // exclusive
}
__global__ void scan3_kernel() {
    int b = blockIdx.x, t = threadIdx.x;
    int i = b * 256 + t;
    if (i < N_NODES) {
        int off = g_boff[b];
        int r = g_rp[i + 1] + off;
        g_rp[i + 1] = r;
        g_wp[i] = r - g_cnt[i];
    }
    if (b == 0 && t == 0) g_rp[0] = 0;
}
__global__ void fill_kernel(const int* __restrict__ ei) {
    int e = blockIdx.x * blockDim.x + threadIdx.x;
    if (e < N_EDGES) {
        int s = ei[e];
        int d = ei[N_EDGES + e];
        int p = atomicAdd(&g_wp[s], 1);
        g_col[p] = d;
    }
}

// ===================== propagation ==========================================
__global__ void init_kernel(const float* __restrict__ x) {
    size_t i = (size_t)blockIdx.x * blockDim.x + threadIdx.x;
    size_t n4 = (size_t)N_NODES * IN_C / 4;
    if (i < n4) {
        float4 v = ((const float4*)x)[i];
        v.x *= 0.5f; v.y *= 0.5f; v.z *= 0.5f; v.w *= 0.5f;
        ((float4*)g_bufF)[i] = v;
    }
}

// Horner hop: tout[r] = f[r] + sum_{j in adj(r)} tin[j]
// last hop (EMIT): emit bf16-split triple of tout/6 directly
template <bool EMIT>
__global__ void spmm_kernel(const float* __restrict__ tin, float* __restrict__ tout) {
    int warp = (blockIdx.x * blockDim.x + threadIdx.x) >> 5;
    int lane = threadIdx.x & 31;
    if (warp >= N_NODES) return;
    int s = g_rp[warp];
    int e = g_rp[warp + 1];
    float4 acc = *(const float4*)(g_bufF + (size_t)warp * IN_C + lane * 4);
    int idx = s;
    for (; idx + 1 < e; idx += 2) {
        int j0 = g_col[idx];
        int j1 = g_col[idx + 1];
        float4 v0 = *(const float4*)(tin + (size_t)j0 * IN_C + lane * 4);
        float4 v1 = *(const float4*)(tin + (size_t)j1 * IN_C + lane * 4);
        acc.x += v0.x + v1.x; acc.y += v0.y + v1.y;
        acc.z += v0.z + v1.z; acc.w += v0.w + v1.w;
    }
    if (idx < e) {
        int j = g_col[idx];
        float4 v = *(const float4*)(tin + (size_t)j * IN_C + lane * 4);
        acc.x += v.x; acc.y += v.y; acc.z += v.z; acc.w += v.w;
    }
    if (!EMIT) {
        *(float4*)(tout + (size_t)warp * IN_C + lane * 4) = acc;
    } else {
        const float sc = 1.0f / 6.0f;
        float a = acc.x * sc, b = acc.y * sc, c = acc.z * sc, d = acc.w * sc;
        float la, lb, lc, ld;
        uint2 h2, l2;
        h2.x = pack_hi2(a, b, la, lb);
        h2.y = pack_hi2(c, d, lc, ld);
        l2.x = pack_bf2(la, lb);
        l2.y = pack_bf2(lc, ld);
        __nv_bfloat16* row = g_a3y + (size_t)warp * (3 * IN_C);
        int c0 = lane * 4;
        *(uint2*)(row + c0)            = h2;
        *(uint2*)(row + IN_C + c0)     = l2;
        *(uint2*)(row + 2 * IN_C + c0) = h2;
    }
}

// W[K,N] fp32 -> Wt3[N, 3K] bf16 = [hi | hi | lo]
__global__ void convw_kernel(const float* __restrict__ W, __nv_bfloat16* __restrict__ Wt3,
                             int K, int N) {
    int i = blockIdx.x * blockDim.x + threadIdx.x;
    if (i >= K * N) return;
    int k = i / N, n = i % N;
    float v = W[i];
    __nv_bfloat16 hi = __float2bfloat16(v);
    __nv_bfloat16 lo = __float2bfloat16(v - __bfloat162float(hi));
    size_t rb = (size_t)n * 3 * K;
    Wt3[rb + k]         = hi;
    Wt3[rb + K + k]     = hi;
    Wt3[rb + 2 * K + k] = lo;
}

// ===================== mma.sync GEMM ========================================
// CTA tile 128 x N_TILE, BK=32, 8 warps (4 x 2), warp tile 32 x (N_TILE/2).
// A3 row-major [M, K3]; Bt3 [N, K3]. NI = N_TILE/16 n-blocks of 8 per warp.
// OUTMODE 0: relu(acc+bias) -> bf16 triple [hi|lo|hi] in outb (row width 768)
// OUTMODE 1: acc+bias (fp32) -> outf (row width 64)
template <int K3, int N_TILE, int OUTMODE>
__global__ void __launch_bounds__(256, 2) mgemm_kernel(
    const __nv_bfloat16* __restrict__ A3, const __nv_bfloat16* __restrict__ Bt3,
    const float* __restrict__ bias, float* __restrict__ outf,
    __nv_bfloat16* __restrict__ outb)
{
    constexpr int NK = K3 / 32;
    constexpr int NI = N_TILE / 16;           // n-blocks of 8 per warp
    constexpr int WTN = N_TILE / 2;           // warp tile cols
    constexpr int AROWB = 80;                 // 32 bf16 + 16B pad
    constexpr int A_STRIDE = 128 * AROWB;
    constexpr int B_STRIDE = N_TILE * AROWB;

    __shared__ __align__(16) unsigned char smA[2 * A_STRIDE];
    __shared__ __align__(16) unsigned char smB[2 * B_STRIDE];
    __shared__ float sbias[N_TILE];

    const int t = threadIdx.x;
    const int lane = t & 31;
    const int wid = t >> 5;
    const int wm = wid & 3;
    const int wn = wid >> 2;
    const int m0 = blockIdx.x * 128;
    const int n0 = blockIdx.y * N_TILE;

    const uint32_t smA_addr = smem_u32(smA);
    const uint32_t smB_addr = smem_u32(smB);

    if (t < N_TILE) sbias[t] = bias[n0 + t];

    float acc[2][NI][4];
#pragma unroll
    for (int mi = 0; mi < 2; ++mi)
#pragma unroll
        for (int ni = 0; ni < NI; ++ni)
#pragma unroll
            for (int q = 0; q < 4; ++q) acc[mi][ni][q] = 0.f;

    auto load_tile = [&](int kbase, int s) {
#pragma unroll
        for (int i = 0; i < 2; ++i) {
            int u = t + i * 256;
            int row = u >> 2, seg = u & 3;
            uint32_t dst = smA_addr + s * A_STRIDE + row * AROWB + seg * 16;
            int m = m0 + row;
            int mc = (m < N_NODES) ? m : 0;
            const __nv_bfloat16* src = A3 + (size_t)mc * K3 + kbase + seg * 8;
            cp16(dst, src, (m < N_NODES) ? 16 : 0);
        }
#pragma unroll
        for (int i = 0; i < N_TILE / 64; ++i) {
            int u = t + i * 256;
            int row = u >> 2, seg = u & 3;
            uint32_t dst = smB_addr + s * B_STRIDE + row * AROWB + seg * 16;
            const __nv_bfloat16* src = Bt3 + (size_t)(n0 + row) * K3 + kbase + seg * 8;
            cp16(dst, src);
        }
    };

    load_tile(0, 0);
    CP_COMMIT();
    CP_WAIT0();
    __syncthreads();

    for (int kt = 0; kt < NK; ++kt) {
        const int s = kt & 1;
        if (kt + 1 < NK) { load_tile((kt + 1) * 32, s ^ 1); CP_COMMIT(); }

        const uint32_t abase0 = smA_addr + s * A_STRIDE +
                                (wm * 32 + (lane & 15)) * AROWB + ((lane >> 4) * 16);
        const uint32_t bbase0 = smB_addr + s * B_STRIDE +
                                (wn * WTN + (lane & 7)) * AROWB + (((lane >> 3) & 1) * 16);
#pragma unroll
        for (int h = 0; h < 2; ++h) {
            uint32_t aF[2][4];
            uint32_t bF[NI][2];
            ldsm_x4(aF[0], abase0 + h * 32);
            ldsm_x4(aF[1], abase0 + h * 32 + 16 * AROWB);
#pragma unroll
            for (int ni = 0; ni < NI; ++ni)
                ldsm_x2(bF[ni], bbase0 + h * 32 + ni * 8 * AROWB);
#pragma unroll
            for (int mi = 0; mi < 2; ++mi)
#pragma unroll
                for (int ni = 0; ni < NI; ++ni)
                    mma_bf16(acc[mi][ni], aF[mi], bF[ni]);
        }

        if (kt + 1 < NK) { CP_WAIT0(); __syncthreads(); }
    }

    // ---------------- epilogue ----------------
    const int lr = lane >> 2;
    const int lc = (lane & 3) * 2;
#pragma unroll
    for (int mi = 0; mi < 2; ++mi) {
#pragma unroll
        for (int half = 0; half < 2; ++half) {
            const int m = m0 + wm * 32 + mi * 16 + lr + half * 8;
            if (m < N_NODES) {
                if (OUTMODE == 0) {
                    __nv_bfloat16* orow = outb + (size_t)m * 768;
#pragma unroll
                    for (int ni = 0; ni < NI; ++ni) {
                        int cl = wn * WTN + ni * 8 + lc;
                        float a = acc[mi][ni][half * 2 + 0] + sbias[cl];
                        float b = acc[mi][ni][half * 2 + 1] + sbias[cl + 1];
                        a = fmaxf(a, 0.f); b = fmaxf(b, 0.f);
                        float la, lb;
                        uint32_t hi = pack_hi2(a, b, la, lb);
                        uint32_t lo = pack_bf2(la, lb);
                        int col = n0 + cl;
                        *(uint32_t*)(orow + col)       = hi;
                        *(uint32_t*)(orow + 256 + col) = lo;
                        *(uint32_t*)(orow + 512 + col) = hi;
                    }
                } else {
#pragma unroll
                    for (int ni = 0; ni < NI; ++ni) {
                        int cl = wn * WTN + ni * 8 + lc;
                        float a = acc[mi][ni][half * 2 + 0] + sbias[cl];
                        float b = acc[mi][ni][half * 2 + 1] + sbias[cl + 1];
                        *(float2*)(outf + (size_t)m * 64 + cl) = make_float2(a, b);
                    }
                }
            }
        }
    }
}

// ---------------- log-softmax over 64 cols, warp per row, in place ----------
__global__ void lsm_kernel(float* __restrict__ out) {
    int warp = (blockIdx.x * blockDim.x + threadIdx.x) >> 5;
    int lane = threadIdx.x & 31;
    if (warp >= N_NODES) return;
    float* row = out + (size_t)warp * OUT_C;
    float v0 = row[lane];
    float v1 = row[lane + 32];
    float m = fmaxf(v0, v1);
#pragma unroll
    for (int off = 16; off > 0; off >>= 1)
        m = fmaxf(m, __shfl_xor_sync(0xFFFFFFFFu, m, off));
    float s = expf(v0 - m) + expf(v1 - m);
#pragma unroll
    for (int off = 16; off > 0; off >>= 1)
        s += __shfl_xor_sync(0xFFFFFFFFu, s, off);
    float l = m + logf(s);
    row[lane]      = v0 - l;
    row[lane + 32] = v1 - l;
}

// ===================== launch ===============================================
extern "C" void kernel_launch(void* const* d_in, const int* in_sizes, int n_in,
                              void* d_out, int out_size) {
    const float* x  = (const float*)d_in[0];
    const int*   ei = (const int*)  d_in[1];
    const float* W1 = (const float*)d_in[2];
    const float* b1 = (const float*)d_in[3];
    const float* W2 = (const float*)d_in[4];
    const float* b2 = (const float*)d_in[5];
    const float* W3 = (const float*)d_in[6];
    const float* b3 = (const float*)d_in[7];
    float* out = (float*)d_out;
    (void)in_sizes; (void)n_in; (void)out_size;

    void *pF, *pA, *pB, *pa3, *ph13, *ph23, *pw1, *pw2, *pw3;
    cudaGetSymbolAddress(&pF,  g_bufF);
    cudaGetSymbolAddress(&pA,  g_bufA);
    cudaGetSymbolAddress(&pB,  g_bufB);
    cudaGetSymbolAddress(&pa3, g_a3y);
    cudaGetSymbolAddress(&ph13, g_h13);
    cudaGetSymbolAddress(&ph23, g_h23);
    cudaGetSymbolAddress(&pw1, g_wt1);
    cudaGetSymbolAddress(&pw2, g_wt2);
    cudaGetSymbolAddress(&pw3, g_wt3);
    float* bufF = (float*)pF;
    float* bufA = (float*)pA;
    float* bufB = (float*)pB;
    __nv_bfloat16* a3y = (__nv_bfloat16*)pa3;
    __nv_bfloat16* h13 = (__nv_bfloat16*)ph13;
    __nv_bfloat16* h23 = (__nv_bfloat16*)ph23;
    __nv_bfloat16* wt1 = (__nv_bfloat16*)pw1;
    __nv_bfloat16* wt2 = (__nv_bfloat16*)pw2;
    __nv_bfloat16* wt3 = (__nv_bfloat16*)pw3;

    // 1) CSR build (two-level scan)
    zero_cnt_kernel<<<(N_NODES + 255) / 256, 256>>>();
    hist_kernel<<<(N_EDGES + 255) / 256, 256>>>(ei);
    scan1_kernel<<<SCAN_BLOCKS, 256>>>();
    scan2_kernel<<<1, 256>>>();
    scan3_kernel<<<SCAN_BLOCKS, 256>>>();
    fill_kernel<<<(N_EDGES + 255) / 256, 256>>>(ei);

    // 2) weight conversions (independent)
    convw_kernel<<<(IN_C * HID_C + 255) / 256, 256>>>(W1, wt1, IN_C, HID_C);
    convw_kernel<<<(HID_C * HID_C + 255) / 256, 256>>>(W2, wt2, HID_C, HID_C);
    convw_kernel<<<(HID_C * OUT_C + 255) / 256, 256>>>(W3, wt3, HID_C, OUT_C);

    // 3) init f
    {
        size_t n4 = (size_t)N_NODES * IN_C / 4;
        init_kernel<<<(int)((n4 + 255) / 256), 256>>>(x);
    }

    // 4) Horner propagation: t_k = f + A t_{k-1}; t0 = f (bufF)
    const int spmm_blocks = (N_NODES * 32 + 255) / 256;
    spmm_kernel<false><<<spmm_blocks, 256>>>(bufF, bufA);
    spmm_kernel<false><<<spmm_blocks, 256>>>(bufA, bufB);
    spmm_kernel<false><<<spmm_blocks, 256>>>(bufB, bufA);
    spmm_kernel<false><<<spmm_blocks, 256>>>(bufA, bufB);
    spmm_kernel<true><<<spmm_blocks, 256>>>(bufB, bufA);

    // 5) MLP on tensor cores (bf16 3-term split), fused bias/relu/split emit
    const int mtiles = (N_NODES + 127) / 128;  // 391
    mgemm_kernel<384, 128, 0><<<dim3(mtiles, HID_C / 128), 256>>>(a3y, wt1, b1, nullptr, h13);
    mgemm_kernel<768, 128, 0><<<dim3(mtiles, HID_C / 128), 256>>>(h13, wt2, b2, nullptr, h23);
    mgemm_kernel<768, 64, 1><<<dim3(mtiles, 1), 256>>>(h23, wt3, b3, out, nullptr);

    // 6) log-softmax in place on d_out
    lsm_kernel<<<(N_NODES * 32 + 255) / 256, 256>>>(out);
}

// round 5
// speedup vs baseline: 1.5880x; 1.0864x over previous
#include <cuda_runtime.h>
#include <cuda_bf16.h>
#include <math.h>
#include <stdint.h>

#define N_NODES 50000
#define N_EDGES 500000
#define IN_C    128
#define HID_C   256
#define OUT_C   64
#define SCAN_BLOCKS ((N_NODES + 255) / 256)   // 196

// ===================== scratch (static device globals) ======================
__device__ int   g_cnt[N_NODES];
__device__ int   g_rp [N_NODES + 1];
__device__ int   g_wp [N_NODES];
__device__ int   g_bsum[SCAN_BLOCKS];
__device__ int   g_boff[SCAN_BLOCKS];
__device__ int   g_col[N_EDGES];
__device__ float g_bufF[(size_t)N_NODES * IN_C];   // f = x * 0.5
__device__ float g_bufA[(size_t)N_NODES * IN_C];   // Horner ping
__device__ float g_bufB[(size_t)N_NODES * IN_C];   // Horner pong
// bf16 split operands: A stored [hi | lo] (2K0 wide); W stored [hi | hi | lo] (3K0)
__device__ __nv_bfloat16 g_a2y [(size_t)N_NODES * (2 * IN_C)];   // 50000 x 256
__device__ __nv_bfloat16 g_h12 [(size_t)N_NODES * (2 * HID_C)];  // 50000 x 512
__device__ __nv_bfloat16 g_h22 [(size_t)N_NODES * (2 * HID_C)];  // 50000 x 512
__device__ __nv_bfloat16 g_wt1 [(size_t)HID_C * (3 * IN_C)];
__device__ __nv_bfloat16 g_wt2 [(size_t)HID_C * (3 * HID_C)];
__device__ __nv_bfloat16 g_wt3 [(size_t)OUT_C * (3 * HID_C)];

// ===================== small helpers ========================================
__device__ __forceinline__ uint32_t smem_u32(const void* p) {
    uint32_t a;
    asm("{ .reg .u64 t; cvta.to.shared.u64 t, %1; cvt.u32.u64 %0, t; }" : "=r"(a) : "l"(p));
    return a;
}
__device__ __forceinline__ uint32_t pack_hi2(float a, float b, float& la, float& lb) {
    __nv_bfloat16 ah = __float2bfloat16(a);
    __nv_bfloat16 bh = __float2bfloat16(b);
    la = a - __bfloat162float(ah);
    lb = b - __bfloat162float(bh);
    __nv_bfloat162 h2; h2.x = ah; h2.y = bh;
    return *(uint32_t*)&h2;
}
__device__ __forceinline__ uint32_t pack_bf2(float a, float b) {
    __nv_bfloat162 h2; h2.x = __float2bfloat16(a); h2.y = __float2bfloat16(b);
    return *(uint32_t*)&h2;
}
__device__ __forceinline__ void ldsm_x4(uint32_t (&r)[4], uint32_t addr) {
    asm volatile("ldmatrix.sync.aligned.m8n8.x4.shared.b16 {%0,%1,%2,%3},[%4];"
                 : "=r"(r[0]), "=r"(r[1]), "=r"(r[2]), "=r"(r[3]) : "r"(addr));
}
__device__ __forceinline__ void ldsm_x2(uint32_t (&r)[2], uint32_t addr) {
    asm volatile("ldmatrix.sync.aligned.m8n8.x2.shared.b16 {%0,%1},[%2];"
                 : "=r"(r[0]), "=r"(r[1]) : "r"(addr));
}
__device__ __forceinline__ void mma_bf16(float (&d)[4], const uint32_t (&a)[4],
                                         const uint32_t (&b)[2]) {
    asm volatile("mma.sync.aligned.m16n8k16.row.col.f32.bf16.bf16.f32 "
                 "{%0,%1,%2,%3},{%4,%5,%6,%7},{%8,%9},{%0,%1,%2,%3};"
                 : "+f"(d[0]), "+f"(d[1]), "+f"(d[2]), "+f"(d[3])
                 : "r"(a[0]), "r"(a[1]), "r"(a[2]), "r"(a[3]), "r"(b[0]), "r"(b[1]));
}
__device__ __forceinline__ void cp16(uint32_t dst, const void* src, int sz) {
    asm volatile("cp.async.cg.shared.global [%0],[%1],16,%2;"
                 :: "r"(dst), "l"(src), "r"(sz) : "memory");
}
__device__ __forceinline__ void cp16(uint32_t dst, const void* src) {
    asm volatile("cp.async.cg.shared.global [%0],[%1],16;"
                 :: "r"(dst), "l"(src) : "memory");
}
#define CP_COMMIT() asm volatile("cp.async.commit_group;" ::: "memory")
#define CP_WAIT0()  asm volatile("cp.async.wait_group 0;" ::: "memory")

// ===================== CSR build ============================================
__global__ void zero_cnt_kernel() {
    int i = blockIdx.x * blockDim.x + threadIdx.x;
    if (i < N_NODES) g_cnt[i] = 0;
}
__global__ void hist_kernel(const int* __restrict__ ei) {
    int e = blockIdx.x * blockDim.x + threadIdx.x;
    if (e < N_EDGES) atomicAdd(&g_cnt[ei[e]], 1);
}
__global__ void scan1_kernel() {
    int b = blockIdx.x, t = threadIdx.x;
    int i = b * 256 + t;
    int lane = t & 31, w = t >> 5;
    int v = (i < N_NODES) ? g_cnt[i] : 0;
    int x = v;
#pragma unroll
    for (int o = 1; o < 32; o <<= 1) {
        int y = __shfl_up_sync(0xFFFFFFFFu, x, o);
        if (lane >= o) x += y;
    }
    __shared__ int ws[8];
    if (lane == 31) ws[w] = x;
    __syncthreads();
    if (w == 0 && lane < 8) {
        int y = ws[lane];
#pragma unroll
        for (int o = 1; o < 8; o <<= 1) {
            int z = __shfl_up_sync(0xFFu, y, o);
            if (lane >= o) y += z;
        }
        ws[lane] = y;
    }
    __syncthreads();
    int incl = x + (w > 0 ? ws[w - 1] : 0);
    if (i < N_NODES) g_rp[i + 1] = incl;
    if (t == 255) g_bsum[b] = incl;
}
__global__ void scan2_kernel() {
    int t = threadIdx.x;
    int lane = t & 31, w = t >> 5;
    int v = (t < SCAN_BLOCKS) ? g_bsum[t] : 0;
    int x = v;
#pragma unroll
    for (int o = 1; o < 32; o <<= 1) {
        int y = __shfl_up_sync(0xFFFFFFFFu, x, o);
        if (lane >= o) x += y;
    }
    __shared__ int ws[8];
    if (lane == 31) ws[w] = x;
    __syncthreads();
    if (w == 0 && lane < 8) {
        int y = ws[lane];
#pragma unroll
        for (int o = 1; o < 8; o <<= 1) {
            int z = __shfl_up_sync(0xFFu, y, o);
            if (lane >= o) y += z;
        }
        ws[lane] = y;
    }
    __syncthreads();
    int incl = x + (w > 0 ? ws[w - 1] : 0);
    if (t < SCAN_BLOCKS) g_boff[t] = incl - v;
}
__global__ void scan3_kernel() {
    int b = blockIdx.x, t = threadIdx.x;
    int i = b * 256 + t;
    if (i < N_NODES) {
        int off = g_boff[b];
        int r = g_rp[i + 1] + off;
        g_rp[i + 1] = r;
        g_wp[i] = r - g_cnt[i];
    }
    if (b == 0 && t == 0) g_rp[0] = 0;
}
__global__ void fill_kernel(const int* __restrict__ ei) {
    int e = blockIdx.x * blockDim.x + threadIdx.x;
    if (e < N_EDGES) {
        int s = ei[e];
        int d = ei[N_EDGES + e];
        int p = atomicAdd(&g_wp[s], 1);
        g_col[p] = d;
    }
}

// ===================== propagation ==========================================
__global__ void init_kernel(const float* __restrict__ x) {
    size_t i = (size_t)blockIdx.x * blockDim.x + threadIdx.x;
    size_t n4 = (size_t)N_NODES * IN_C / 4;
    if (i < n4) {
        float4 v = ((const float4*)x)[i];
        v.x *= 0.5f; v.y *= 0.5f; v.z *= 0.5f; v.w *= 0.5f;
        ((float4*)g_bufF)[i] = v;
    }
}

// Horner hop: tout[r] = f[r] + sum_{j in adj(r)} tin[j]
// last hop (EMIT): emit bf16 [hi|lo] of tout/6 directly
template <bool EMIT>
__global__ void spmm_kernel(const float* __restrict__ tin, float* __restrict__ tout) {
    int warp = (blockIdx.x * blockDim.x + threadIdx.x) >> 5;
    int lane = threadIdx.x & 31;
    if (warp >= N_NODES) return;
    int s = g_rp[warp];
    int e = g_rp[warp + 1];
    float4 acc = *(const float4*)(g_bufF + (size_t)warp * IN_C + lane * 4);
    int idx = s;
    for (; idx + 1 < e; idx += 2) {
        int j0 = g_col[idx];
        int j1 = g_col[idx + 1];
        float4 v0 = *(const float4*)(tin + (size_t)j0 * IN_C + lane * 4);
        float4 v1 = *(const float4*)(tin + (size_t)j1 * IN_C + lane * 4);
        acc.x += v0.x + v1.x; acc.y += v0.y + v1.y;
        acc.z += v0.z + v1.z; acc.w += v0.w + v1.w;
    }
    if (idx < e) {
        int j = g_col[idx];
        float4 v = *(const float4*)(tin + (size_t)j * IN_C + lane * 4);
        acc.x += v.x; acc.y += v.y; acc.z += v.z; acc.w += v.w;
    }
    if (!EMIT) {
        *(float4*)(tout + (size_t)warp * IN_C + lane * 4) = acc;
    } else {
        const float sc = 1.0f / 6.0f;
        float a = acc.x * sc, b = acc.y * sc, c = acc.z * sc, d = acc.w * sc;
        float la, lb, lc, ld;
        uint2 h2, l2;
        h2.x = pack_hi2(a, b, la, lb);
        h2.y = pack_hi2(c, d, lc, ld);
        l2.x = pack_bf2(la, lb);
        l2.y = pack_bf2(lc, ld);
        __nv_bfloat16* row = g_a2y + (size_t)warp * (2 * IN_C);
        int c0 = lane * 4;
        *(uint2*)(row + c0)        = h2;
        *(uint2*)(row + IN_C + c0) = l2;
    }
}

// W[K,N] fp32 -> Wt3[N, 3K] bf16 = [hi | hi | lo]
__global__ void convw_kernel(const float* __restrict__ W, __nv_bfloat16* __restrict__ Wt3,
                             int K, int N) {
    int i = blockIdx.x * blockDim.x + threadIdx.x;
    if (i >= K * N) return;
    int k = i / N, n = i % N;
    float v = W[i];
    __nv_bfloat16 hi = __float2bfloat16(v);
    __nv_bfloat16 lo = __float2bfloat16(v - __bfloat162float(hi));
    size_t rb = (size_t)n * 3 * K;
    Wt3[rb + k]         = hi;
    Wt3[rb + K + k]     = hi;
    Wt3[rb + 2 * K + k] = lo;
}

// ===================== mma.sync GEMM ========================================
// CTA tile 128 x N_TILE, BK=32, 8 warps (4 x 2), warp tile 32 x (N_TILE/2).
// Logical K = LOGK (= 3*K0); A physically [hi|lo] width APHYS (= 2*K0):
//   kphys = kbase >= APHYS ? kbase - APHYS : kbase   (third block re-reads hi)
// W stored [hi|hi|lo] width LOGK.
// OUTMODE 0: relu(acc+bias) -> bf16 pair [hi|lo] in outb (row width 2*HID_C)
// OUTMODE 1: fused log-softmax(acc+bias) -> fp32 outf (row width 64)
template <int LOGK, int APHYS, int N_TILE, int OUTMODE>
__global__ void __launch_bounds__(256, 2) mgemm_kernel(
    const __nv_bfloat16* __restrict__ A2, const __nv_bfloat16* __restrict__ Bt3,
    const float* __restrict__ bias, float* __restrict__ outf,
    __nv_bfloat16* __restrict__ outb)
{
    constexpr int NK = LOGK / 32;
    constexpr int NI = N_TILE / 16;
    constexpr int WTN = N_TILE / 2;
    constexpr int AROWB = 80;                 // 32 bf16 + 16B pad
    constexpr int A_STRIDE = 128 * AROWB;
    constexpr int B_STRIDE = N_TILE * AROWB;
    constexpr int TILE_BYTES = 2 * A_STRIDE + 2 * B_STRIDE;
    constexpr int SLOG_BYTES = (OUTMODE == 1) ? (128 * 66 * 4) : 0;
    constexpr int SMEM_BYTES = (TILE_BYTES > SLOG_BYTES) ? TILE_BYTES : SLOG_BYTES;

    __shared__ __align__(16) unsigned char smem[SMEM_BYTES];
    __shared__ float sbias[N_TILE];

    unsigned char* smA = smem;
    unsigned char* smB = smem + 2 * A_STRIDE;

    const int t = threadIdx.x;
    const int lane = t & 31;
    const int wid = t >> 5;
    const int wm = wid & 3;
    const int wn = wid >> 2;
    const int m0 = blockIdx.x * 128;
    const int n0 = blockIdx.y * N_TILE;

    const uint32_t smA_addr = smem_u32(smA);
    const uint32_t smB_addr = smem_u32(smB);

    if (t < N_TILE) sbias[t] = bias[n0 + t];

    float acc[2][NI][4];
#pragma unroll
    for (int mi = 0; mi < 2; ++mi)
#pragma unroll
        for (int ni = 0; ni < NI; ++ni)
#pragma unroll
            for (int q = 0; q < 4; ++q) acc[mi][ni][q] = 0.f;

    auto load_tile = [&](int kbase, int s) {
        const int kphys = (kbase >= APHYS) ? (kbase - APHYS) : kbase;
#pragma unroll
        for (int i = 0; i < 2; ++i) {
            int u = t + i * 256;
            int row = u >> 2, seg = u & 3;
            uint32_t dst = smA_addr + s * A_STRIDE + row * AROWB + seg * 16;
            int m = m0 + row;
            int mc = (m < N_NODES) ? m : 0;
            const __nv_bfloat16* src = A2 + (size_t)mc * APHYS + kphys + seg * 8;
            cp16(dst, src, (m < N_NODES) ? 16 : 0);
        }
#pragma unroll
        for (int i = 0; i < N_TILE / 64; ++i) {
            int u = t + i * 256;
            int row = u >> 2, seg = u & 3;
            uint32_t dst = smB_addr + s * B_STRIDE + row * AROWB + seg * 16;
            const __nv_bfloat16* src = Bt3 + (size_t)(n0 + row) * LOGK + kbase + seg * 8;
            cp16(dst, src);
        }
    };

    load_tile(0, 0);
    CP_COMMIT();
    CP_WAIT0();
    __syncthreads();

    for (int kt = 0; kt < NK; ++kt) {
        const int s = kt & 1;
        if (kt + 1 < NK) { load_tile((kt + 1) * 32, s ^ 1); CP_COMMIT(); }

        const uint32_t abase0 = smA_addr + s * A_STRIDE +
                                (wm * 32 + (lane & 15)) * AROWB + ((lane >> 4) * 16);
        const uint32_t bbase0 = smB_addr + s * B_STRIDE +
                                (wn * WTN + (lane & 7)) * AROWB + (((lane >> 3) & 1) * 16);
#pragma unroll
        for (int h = 0; h < 2; ++h) {
            uint32_t aF[2][4];
            uint32_t bF[NI][2];
            ldsm_x4(aF[0], abase0 + h * 32);
            ldsm_x4(aF[1], abase0 + h * 32 + 16 * AROWB);
#pragma unroll
            for (int ni = 0; ni < NI; ++ni)
                ldsm_x2(bF[ni], bbase0 + h * 32 + ni * 8 * AROWB);
#pragma unroll
            for (int mi = 0; mi < 2; ++mi)
#pragma unroll
                for (int ni = 0; ni < NI; ++ni)
                    mma_bf16(acc[mi][ni], aF[mi], bF[ni]);
        }

        if (kt + 1 < NK) { CP_WAIT0(); __syncthreads(); }
    }

    // ---------------- epilogue ----------------
    const int lr = lane >> 2;
    const int lc = (lane & 3) * 2;
    if (OUTMODE == 0) {
#pragma unroll
        for (int mi = 0; mi < 2; ++mi) {
#pragma unroll
            for (int half = 0; half < 2; ++half) {
                const int m = m0 + wm * 32 + mi * 16 + lr + half * 8;
                if (m < N_NODES) {
                    __nv_bfloat16* orow = outb + (size_t)m * (2 * HID_C);
#pragma unroll
                    for (int ni = 0; ni < NI; ++ni) {
                        int cl = wn * WTN + ni * 8 + lc;
                        float a = acc[mi][ni][half * 2 + 0] + sbias[cl];
                        float b = acc[mi][ni][half * 2 + 1] + sbias[cl + 1];
                        a = fmaxf(a, 0.f); b = fmaxf(b, 0.f);
                        float la, lb;
                        uint32_t hi = pack_hi2(a, b, la, lb);
                        uint32_t lo = pack_bf2(la, lb);
                        int col = n0 + cl;
                        *(uint32_t*)(orow + col)         = hi;
                        *(uint32_t*)(orow + HID_C + col) = lo;
                    }
                }
            }
        }
    } else {
        // stage logits in smem (tiles dead now), then fused log-softmax
        float* slog = (float*)smem;
        __syncthreads();   // all warps done reading tile smem
#pragma unroll
        for (int mi = 0; mi < 2; ++mi) {
#pragma unroll
            for (int half = 0; half < 2; ++half) {
                const int r = wm * 32 + mi * 16 + lr + half * 8;
#pragma unroll
                for (int ni = 0; ni < NI; ++ni) {
                    int cl = wn * WTN + ni * 8 + lc;
                    float a = acc[mi][ni][half * 2 + 0] + sbias[cl];
                    float b = acc[mi][ni][half * 2 + 1] + sbias[cl + 1];
                    *(float2*)(slog + r * 66 + cl) = make_float2(a, b);
                }
            }
        }
        __syncthreads();
#pragma unroll
        for (int rr = 0; rr < 16; ++rr) {
            int r = wid * 16 + rr;
            int m = m0 + r;
            float v0 = slog[r * 66 + lane];
            float v1 = slog[r * 66 + lane + 32];
            float mx = fmaxf(v0, v1);
#pragma unroll
            for (int off = 16; off > 0; off >>= 1)
                mx = fmaxf(mx, __shfl_xor_sync(0xFFFFFFFFu, mx, off));
            float sm = expf(v0 - mx) + expf(v1 - mx);
#pragma unroll
            for (int off = 16; off > 0; off >>= 1)
                sm += __shfl_xor_sync(0xFFFFFFFFu, sm, off);
            float l = mx + logf(sm);
            if (m < N_NODES) {
                outf[(size_t)m * 64 + lane]      = v0 - l;
                outf[(size_t)m * 64 + lane + 32] = v1 - l;
            }
        }
    }
}

// ===================== launch ===============================================
extern "C" void kernel_launch(void* const* d_in, const int* in_sizes, int n_in,
                              void* d_out, int out_size) {
    const float* x  = (const float*)d_in[0];
    const int*   ei = (const int*)  d_in[1];
    const float* W1 = (const float*)d_in[2];
    const float* b1 = (const float*)d_in[3];
    const float* W2 = (const float*)d_in[4];
    const float* b2 = (const float*)d_in[5];
    const float* W3 = (const float*)d_in[6];
    const float* b3 = (const float*)d_in[7];
    float* out = (float*)d_out;
    (void)in_sizes; (void)n_in; (void)out_size;

    void *pF, *pA, *pB, *pa2, *ph12, *ph22, *pw1, *pw2, *pw3;
    cudaGetSymbolAddress(&pF,  g_bufF);
    cudaGetSymbolAddress(&pA,  g_bufA);
    cudaGetSymbolAddress(&pB,  g_bufB);
    cudaGetSymbolAddress(&pa2, g_a2y);
    cudaGetSymbolAddress(&ph12, g_h12);
    cudaGetSymbolAddress(&ph22, g_h22);
    cudaGetSymbolAddress(&pw1, g_wt1);
    cudaGetSymbolAddress(&pw2, g_wt2);
    cudaGetSymbolAddress(&pw3, g_wt3);
    float* bufF = (float*)pF;
    float* bufA = (float*)pA;
    float* bufB = (float*)pB;
    __nv_bfloat16* a2y = (__nv_bfloat16*)pa2;
    __nv_bfloat16* h12 = (__nv_bfloat16*)ph12;
    __nv_bfloat16* h22 = (__nv_bfloat16*)ph22;
    __nv_bfloat16* wt1 = (__nv_bfloat16*)pw1;
    __nv_bfloat16* wt2 = (__nv_bfloat16*)pw2;
    __nv_bfloat16* wt3 = (__nv_bfloat16*)pw3;

    // 1) CSR build (two-level scan)
    zero_cnt_kernel<<<(N_NODES + 255) / 256, 256>>>();
    hist_kernel<<<(N_EDGES + 255) / 256, 256>>>(ei);
    scan1_kernel<<<SCAN_BLOCKS, 256>>>();
    scan2_kernel<<<1, 256>>>();
    scan3_kernel<<<SCAN_BLOCKS, 256>>>();
    fill_kernel<<<(N_EDGES + 255) / 256, 256>>>(ei);

    // 2) weight conversions
    convw_kernel<<<(IN_C * HID_C + 255) / 256, 256>>>(W1, wt1, IN_C, HID_C);
    convw_kernel<<<(HID_C * HID_C + 255) / 256, 256>>>(W2, wt2, HID_C, HID_C);
    convw_kernel<<<(HID_C * OUT_C + 255) / 256, 256>>>(W3, wt3, HID_C, OUT_C);

    // 3) init f
    {
        size_t n4 = (size_t)N_NODES * IN_C / 4;
        init_kernel<<<(int)((n4 + 255) / 256), 256>>>(x);
    }

    // 4) Horner propagation: t_k = f + A t_{k-1}; t0 = f
    const int spmm_blocks = (N_NODES * 32 + 255) / 256;
    spmm_kernel<false><<<spmm_blocks, 256>>>(bufF, bufA);
    spmm_kernel<false><<<spmm_blocks, 256>>>(bufA, bufB);
    spmm_kernel<false><<<spmm_blocks, 256>>>(bufB, bufA);
    spmm_kernel<false><<<spmm_blocks, 256>>>(bufA, bufB);
    spmm_kernel<true><<<spmm_blocks, 256>>>(bufB, bufA);

    // 5) MLP on tensor cores (bf16 3-term split, A stored [hi|lo])
    const int mtiles = (N_NODES + 127) / 128;  // 391
    mgemm_kernel<384, 256, 128, 0><<<dim3(mtiles, HID_C / 128), 256>>>(a2y, wt1, b1, nullptr, h12);
    mgemm_kernel<768, 512, 128, 0><<<dim3(mtiles, HID_C / 128), 256>>>(h12, wt2, b2, nullptr, h22);
    mgemm_kernel<768, 512, 64, 1><<<dim3(mtiles, 1), 256>>>(h22, wt3, b3, out, nullptr);
}

// round 6
// speedup vs baseline: 1.5886x; 1.0004x over previous
#include <cuda_runtime.h>
#include <cuda_bf16.h>
#include <math.h>
#include <stdint.h>

#define N_NODES 50000
#define N_EDGES 500000
#define IN_C    128
#define HID_C   256
#define OUT_C   64
#define SCAN_BLOCKS ((N_NODES + 255) / 256)   // 196
#define INIT_BLOCKS (((size_t)N_NODES * IN_C / 4 + 255) / 256)  // 6250

// ===================== scratch (static device globals) ======================
__device__ int   g_cnt[N_NODES];
__device__ int   g_rp [N_NODES + 1];
__device__ int   g_wp [N_NODES];
__device__ int   g_bsum[SCAN_BLOCKS];
__device__ int   g_col[N_EDGES];
__device__ float g_bufF[(size_t)N_NODES * IN_C];   // f = x * 0.5
__device__ float g_bufA[(size_t)N_NODES * IN_C];   // Horner ping
__device__ float g_bufB[(size_t)N_NODES * IN_C];   // Horner pong
// bf16 split operands: A stored [hi | lo] (2K0 wide); W stored [hi | hi | lo] (3K0)
__device__ __nv_bfloat16 g_a2y [(size_t)N_NODES * (2 * IN_C)];   // 50000 x 256
__device__ __nv_bfloat16 g_h12 [(size_t)N_NODES * (2 * HID_C)];  // 50000 x 512
__device__ __nv_bfloat16 g_h22 [(size_t)N_NODES * (2 * HID_C)];  // 50000 x 512
__device__ __nv_bfloat16 g_wt1 [(size_t)HID_C * (3 * IN_C)];
__device__ __nv_bfloat16 g_wt2 [(size_t)HID_C * (3 * HID_C)];
__device__ __nv_bfloat16 g_wt3 [(size_t)OUT_C * (3 * HID_C)];

// ===================== small helpers ========================================
__device__ __forceinline__ uint32_t smem_u32(const void* p) {
    uint32_t a;
    asm("{ .reg .u64 t; cvta.to.shared.u64 t, %1; cvt.u32.u64 %0, t; }" : "=r"(a) : "l"(p));
    return a;
}
__device__ __forceinline__ uint32_t pack_hi2(float a, float b, float& la, float& lb) {
    __nv_bfloat16 ah = __float2bfloat16(a);
    __nv_bfloat16 bh = __float2bfloat16(b);
    la = a - __bfloat162float(ah);
    lb = b - __bfloat162float(bh);
    __nv_bfloat162 h2; h2.x = ah; h2.y = bh;
    return *(uint32_t*)&h2;
}
__device__ __forceinline__ uint32_t pack_bf2(float a, float b) {
    __nv_bfloat162 h2; h2.x = __float2bfloat16(a); h2.y = __float2bfloat16(b);
    return *(uint32_t*)&h2;
}
__device__ __forceinline__ void ldsm_x4(uint32_t (&r)[4], uint32_t addr) {
    asm volatile("ldmatrix.sync.aligned.m8n8.x4.shared.b16 {%0,%1,%2,%3},[%4];"
                 : "=r"(r[0]), "=r"(r[1]), "=r"(r[2]), "=r"(r[3]) : "r"(addr));
}
__device__ __forceinline__ void ldsm_x2(uint32_t (&r)[2], uint32_t addr) {
    asm volatile("ldmatrix.sync.aligned.m8n8.x2.shared.b16 {%0,%1},[%2];"
                 : "=r"(r[0]), "=r"(r[1]) : "r"(addr));
}
__device__ __forceinline__ void mma_bf16(float (&d)[4], const uint32_t (&a)[4],
                                         const uint32_t (&b)[2]) {
    asm volatile("mma.sync.aligned.m16n8k16.row.col.f32.bf16.bf16.f32 "
                 "{%0,%1,%2,%3},{%4,%5,%6,%7},{%8,%9},{%0,%1,%2,%3};"
                 : "+f"(d[0]), "+f"(d[1]), "+f"(d[2]), "+f"(d[3])
                 : "r"(a[0]), "r"(a[1]), "r"(a[2]), "r"(a[3]), "r"(b[0]), "r"(b[1]));
}
__device__ __forceinline__ void cp16(uint32_t dst, const void* src, int sz) {
    asm volatile("cp.async.cg.shared.global [%0],[%1],16,%2;"
                 :: "r"(dst), "l"(src), "r"(sz) : "memory");
}
__device__ __forceinline__ void cp16(uint32_t dst, const void* src) {
    asm volatile("cp.async.cg.shared.global [%0],[%1],16;"
                 :: "r"(dst), "l"(src) : "memory");
}
#define CP_COMMIT() asm volatile("cp.async.commit_group;" ::: "memory")
#define CP_WAIT0()  asm volatile("cp.async.wait_group 0;" ::: "memory")

// ===================== prep: zero cnt + init f ==============================
__global__ void prep_kernel(const float* __restrict__ x) {
    int b = blockIdx.x;
    if (b < SCAN_BLOCKS) {
        int i = b * 256 + threadIdx.x;
        if (i < N_NODES) g_cnt[i] = 0;
    } else {
        size_t i = (size_t)(b - SCAN_BLOCKS) * 256 + threadIdx.x;
        size_t n4 = (size_t)N_NODES * IN_C / 4;
        if (i < n4) {
            float4 v = ((const float4*)x)[i];
            v.x *= 0.5f; v.y *= 0.5f; v.z *= 0.5f; v.w *= 0.5f;
            ((float4*)g_bufF)[i] = v;
        }
    }
}

// ===================== CSR build ============================================
__global__ void hist_kernel(const int* __restrict__ ei) {
    int e = blockIdx.x * blockDim.x + threadIdx.x;
    if (e < N_EDGES) atomicAdd(&g_cnt[ei[e]], 1);
}
__global__ void scan1_kernel() {
    int b = blockIdx.x, t = threadIdx.x;
    int i = b * 256 + t;
    int lane = t & 31, w = t >> 5;
    int v = (i < N_NODES) ? g_cnt[i] : 0;
    int x = v;
#pragma unroll
    for (int o = 1; o < 32; o <<= 1) {
        int y = __shfl_up_sync(0xFFFFFFFFu, x, o);
        if (lane >= o) x += y;
    }
    __shared__ int ws[8];
    if (lane == 31) ws[w] = x;
    __syncthreads();
    if (w == 0 && lane < 8) {
        int y = ws[lane];
#pragma unroll
        for (int o = 1; o < 8; o <<= 1) {
            int z = __shfl_up_sync(0xFFu, y, o);
            if (lane >= o) y += z;
        }
        ws[lane] = y;
    }
    __syncthreads();
    int incl = x + (w > 0 ? ws[w - 1] : 0);
    if (i < N_NODES) g_rp[i + 1] = incl;
    if (t == 255) g_bsum[b] = incl;
}
// fused scan2+scan3: every block redundantly scans the 196 block sums
__global__ void scan3f_kernel() {
    int t = threadIdx.x;
    int lane = t & 31, w = t >> 5;
    int v = (t < SCAN_BLOCKS) ? g_bsum[t] : 0;
    int x = v;
#pragma unroll
    for (int o = 1; o < 32; o <<= 1) {
        int y = __shfl_up_sync(0xFFFFFFFFu, x, o);
        if (lane >= o) x += y;
    }
    __shared__ int ws[8];
    __shared__ int sincl[256];
    if (lane == 31) ws[w] = x;
    __syncthreads();
    if (w == 0 && lane < 8) {
        int y = ws[lane];
#pragma unroll
        for (int o = 1; o < 8; o <<= 1) {
            int z = __shfl_up_sync(0xFFu, y, o);
            if (lane >= o) y += z;
        }
        ws[lane] = y;
    }
    __syncthreads();
    sincl[t] = x + (w > 0 ? ws[w - 1] : 0);
    __syncthreads();
    int b = blockIdx.x;
    int off = (b == 0) ? 0 : sincl[b - 1];
    int i = b * 256 + t;
    if (i < N_NODES) {
        int r = g_rp[i + 1] + off;
        g_rp[i + 1] = r;
        g_wp[i] = r - g_cnt[i];
    }
    if (b == 0 && t == 0) g_rp[0] = 0;
}
__global__ void fill_kernel(const int* __restrict__ ei) {
    int e = blockIdx.x * blockDim.x + threadIdx.x;
    if (e < N_EDGES) {
        int s = ei[e];
        int d = ei[N_EDGES + e];
        int p = atomicAdd(&g_wp[s], 1);
        g_col[p] = d;
    }
}

// ===================== propagation ==========================================
// Horner hop: tout[r] = f[r] + sum_{j in adj(r)} tin[j]
// last hop (EMIT): emit bf16 [hi|lo] of tout/6 directly
template <bool EMIT>
__global__ void spmm_kernel(const float* __restrict__ tin, float* __restrict__ tout) {
    int warp = (blockIdx.x * blockDim.x + threadIdx.x) >> 5;
    int lane = threadIdx.x & 31;
    if (warp >= N_NODES) return;
    int s = g_rp[warp];
    int e = g_rp[warp + 1];
    float4 acc = *(const float4*)(g_bufF + (size_t)warp * IN_C + lane * 4);
    int idx = s;
    for (; idx + 3 < e; idx += 4) {
        int j0 = g_col[idx];
        int j1 = g_col[idx + 1];
        int j2 = g_col[idx + 2];
        int j3 = g_col[idx + 3];
        float4 v0 = *(const float4*)(tin + (size_t)j0 * IN_C + lane * 4);
        float4 v1 = *(const float4*)(tin + (size_t)j1 * IN_C + lane * 4);
        float4 v2 = *(const float4*)(tin + (size_t)j2 * IN_C + lane * 4);
        float4 v3 = *(const float4*)(tin + (size_t)j3 * IN_C + lane * 4);
        acc.x += (v0.x + v1.x) + (v2.x + v3.x);
        acc.y += (v0.y + v1.y) + (v2.y + v3.y);
        acc.z += (v0.z + v1.z) + (v2.z + v3.z);
        acc.w += (v0.w + v1.w) + (v2.w + v3.w);
    }
    for (; idx < e; ++idx) {
        int j = g_col[idx];
        float4 v = *(const float4*)(tin + (size_t)j * IN_C + lane * 4);
        acc.x += v.x; acc.y += v.y; acc.z += v.z; acc.w += v.w;
    }
    if (!EMIT) {
        *(float4*)(tout + (size_t)warp * IN_C + lane * 4) = acc;
    } else {
        const float sc = 1.0f / 6.0f;
        float a = acc.x * sc, b = acc.y * sc, c = acc.z * sc, d = acc.w * sc;
        float la, lb, lc, ld;
        uint2 h2, l2;
        h2.x = pack_hi2(a, b, la, lb);
        h2.y = pack_hi2(c, d, lc, ld);
        l2.x = pack_bf2(la, lb);
        l2.y = pack_bf2(lc, ld);
        __nv_bfloat16* row = g_a2y + (size_t)warp * (2 * IN_C);
        int c0 = lane * 4;
        *(uint2*)(row + c0)        = h2;
        *(uint2*)(row + IN_C + c0) = l2;
    }
}

// ===================== fused weight conversion ==============================
__device__ __forceinline__ void conv_one(const float* __restrict__ W,
                                         __nv_bfloat16* __restrict__ Wt3,
                                         int K, int N, int i) {
    int k = i / N, n = i % N;
    float v = W[i];
    __nv_bfloat16 hi = __float2bfloat16(v);
    __nv_bfloat16 lo = __float2bfloat16(v - __bfloat162float(hi));
    size_t rb = (size_t)n * 3 * K;
    Wt3[rb + k]         = hi;
    Wt3[rb + K + k]     = hi;
    Wt3[rb + 2 * K + k] = lo;
}
__global__ void convw_all_kernel(const float* __restrict__ W1,
                                 const float* __restrict__ W2,
                                 const float* __restrict__ W3) {
    int i = blockIdx.x * blockDim.x + threadIdx.x;
    const int n1 = IN_C * HID_C;            // 32768
    const int n2 = n1 + HID_C * HID_C;      // 98304
    const int n3 = n2 + HID_C * OUT_C;      // 114688
    if (i < n1)      conv_one(W1, g_wt1, IN_C,  HID_C, i);
    else if (i < n2) conv_one(W2, g_wt2, HID_C, HID_C, i - n1);
    else if (i < n3) conv_one(W3, g_wt3, HID_C, OUT_C, i - n2);
}

// ===================== mma.sync GEMM ========================================
// CTA tile 128 x N_TILE (full N in one pass), BK=32, THREADS/32 warps in a
// 4 x (THREADS/128) grid; warp tile 32 x WTN.
// Logical K = LOGK (= 3*K0); A physically [hi|lo] width APHYS (= 2*K0):
//   kphys = kbase >= APHYS ? kbase - APHYS : kbase  (third block re-reads hi)
// W stored [hi|hi|lo] width LOGK.
// OUTMODE 0: relu(acc+bias) -> bf16 pair [hi|lo] in outb (row width 2*HID_C)
// OUTMODE 1: fused log-softmax(acc+bias) -> fp32 outf (row width 64)
template <int LOGK, int APHYS, int N_TILE, int THREADS, int OUTMODE>
__global__ void __launch_bounds__(THREADS, (THREADS == 512) ? 1 : 2) mgemm_kernel(
    const __nv_bfloat16* __restrict__ A2, const __nv_bfloat16* __restrict__ Bt3,
    const float* __restrict__ bias, float* __restrict__ outf,
    __nv_bfloat16* __restrict__ outb)
{
    constexpr int NK = LOGK / 32;
    constexpr int WARPS_N = THREADS / 128;    // 4 (gemm1/2) or 2 (gemm3)
    constexpr int WTN = N_TILE / WARPS_N;     // 64 or 32
    constexpr int NI = WTN / 8;               // 8 or 4
    constexpr int AROWB = 80;                 // 32 bf16 + 16B pad
    constexpr int A_STRIDE = 128 * AROWB;
    constexpr int B_STRIDE = N_TILE * AROWB;

    extern __shared__ __align__(16) unsigned char smem[];
    __shared__ float sbias[N_TILE];

    unsigned char* smA = smem;
    unsigned char* smB = smem + 2 * A_STRIDE;

    const int t = threadIdx.x;
    const int lane = t & 31;
    const int wid = t >> 5;
    const int wm = wid & 3;
    const int wn = wid >> 2;
    const int m0 = blockIdx.x * 128;

    const uint32_t smA_addr = smem_u32(smA);
    const uint32_t smB_addr = smem_u32(smB);

    if (t < N_TILE) sbias[t] = bias[t];

    float acc[2][NI][4];
#pragma unroll
    for (int mi = 0; mi < 2; ++mi)
#pragma unroll
        for (int ni = 0; ni < NI; ++ni)
#pragma unroll
            for (int q = 0; q < 4; ++q) acc[mi][ni][q] = 0.f;

    auto load_tile = [&](int kbase, int s) {
        const int kphys = (kbase >= APHYS) ? (kbase - APHYS) : kbase;
#pragma unroll
        for (int u = t; u < 512; u += THREADS) {
            int row = u >> 2, seg = u & 3;
            uint32_t dst = smA_addr + s * A_STRIDE + row * AROWB + seg * 16;
            int m = m0 + row;
            int mc = (m < N_NODES) ? m : 0;
            const __nv_bfloat16* src = A2 + (size_t)mc * APHYS + kphys + seg * 8;
            cp16(dst, src, (m < N_NODES) ? 16 : 0);
        }
#pragma unroll
        for (int u = t; u < N_TILE * 4; u += THREADS) {
            int row = u >> 2, seg = u & 3;
            uint32_t dst = smB_addr + s * B_STRIDE + row * AROWB + seg * 16;
            const __nv_bfloat16* src = Bt3 + (size_t)row * LOGK + kbase + seg * 8;
            cp16(dst, src);
        }
    };

    load_tile(0, 0);
    CP_COMMIT();
    CP_WAIT0();
    __syncthreads();

    for (int kt = 0; kt < NK; ++kt) {
        const int s = kt & 1;
        if (kt + 1 < NK) { load_tile((kt + 1) * 32, s ^ 1); CP_COMMIT(); }

        const uint32_t abase0 = smA_addr + s * A_STRIDE +
                                (wm * 32 + (lane & 15)) * AROWB + ((lane >> 4) * 16);
        const uint32_t bbase0 = smB_addr + s * B_STRIDE +
                                (wn * WTN + (lane & 7)) * AROWB + (((lane >> 3) & 1) * 16);
#pragma unroll
        for (int h = 0; h < 2; ++h) {
            uint32_t aF[2][4];
            uint32_t bF[NI][2];
            ldsm_x4(aF[0], abase0 + h * 32);
            ldsm_x4(aF[1], abase0 + h * 32 + 16 * AROWB);
#pragma unroll
            for (int ni = 0; ni < NI; ++ni)
                ldsm_x2(bF[ni], bbase0 + h * 32 + ni * 8 * AROWB);
#pragma unroll
            for (int mi = 0; mi < 2; ++mi)
#pragma unroll
                for (int ni = 0; ni < NI; ++ni)
                    mma_bf16(acc[mi][ni], aF[mi], bF[ni]);
        }

        if (kt + 1 < NK) { CP_WAIT0(); __syncthreads(); }
    }

    // ---------------- epilogue ----------------
    const int lr = lane >> 2;
    const int lc = (lane & 3) * 2;
    if (OUTMODE == 0) {
#pragma unroll
        for (int mi = 0; mi < 2; ++mi) {
#pragma unroll
            for (int half = 0; half < 2; ++half) {
                const int m = m0 + wm * 32 + mi * 16 + lr + half * 8;
                if (m < N_NODES) {
                    __nv_bfloat16* orow = outb + (size_t)m * (2 * HID_C);
#pragma unroll
                    for (int ni = 0; ni < NI; ++ni) {
                        int cl = wn * WTN + ni * 8 + lc;
                        float a = acc[mi][ni][half * 2 + 0] + sbias[cl];
                        float b = acc[mi][ni][half * 2 + 1] + sbias[cl + 1];
                        a = fmaxf(a, 0.f); b = fmaxf(b, 0.f);
                        float la, lb;
                        uint32_t hi = pack_hi2(a, b, la, lb);
                        uint32_t lo = pack_bf2(la, lb);
                        *(uint32_t*)(orow + cl)         = hi;
                        *(uint32_t*)(orow + HID_C + cl) = lo;
                    }
                }
            }
        }
    } else {
        // stage logits in smem (tiles dead now), then fused log-softmax
        float* slog = (float*)smem;
        __syncthreads();   // all warps done reading tile smem
#pragma unroll
        for (int mi = 0; mi < 2; ++mi) {
#pragma unroll
            for (int half = 0; half < 2; ++half) {
                const int r = wm * 32 + mi * 16 + lr + half * 8;
#pragma unroll
                for (int ni = 0; ni < NI; ++ni) {
                    int cl = wn * WTN + ni * 8 + lc;
                    float a = acc[mi][ni][half * 2 + 0] + sbias[cl];
                    float b = acc[mi][ni][half * 2 + 1] + sbias[cl + 1];
                    *(float2*)(slog + r * 66 + cl) = make_float2(a, b);
                }
            }
        }
        __syncthreads();
#pragma unroll
        for (int rr = 0; rr < 16; ++rr) {
            int r = wid * 16 + rr;
            int m = m0 + r;
            float v0 = slog[r * 66 + lane];
            float v1 = slog[r * 66 + lane + 32];
            float mx = fmaxf(v0, v1);
#pragma unroll
            for (int off = 16; off > 0; off >>= 1)
                mx = fmaxf(mx, __shfl_xor_sync(0xFFFFFFFFu, mx, off));
            float sm = expf(v0 - mx) + expf(v1 - mx);
#pragma unroll
            for (int off = 16; off > 0; off >>= 1)
                sm += __shfl_xor_sync(0xFFFFFFFFu, sm, off);
            float l = mx + logf(sm);
            if (m < N_NODES) {
                outf[(size_t)m * 64 + lane]      = v0 - l;
                outf[(size_t)m * 64 + lane + 32] = v1 - l;
            }
        }
    }
}

// ===================== launch ===============================================
extern "C" void kernel_launch(void* const* d_in, const int* in_sizes, int n_in,
                              void* d_out, int out_size) {
    const float* x  = (const float*)d_in[0];
    const int*   ei = (const int*)  d_in[1];
    const float* W1 = (const float*)d_in[2];
    const float* b1 = (const float*)d_in[3];
    const float* W2 = (const float*)d_in[4];
    const float* b2 = (const float*)d_in[5];
    const float* W3 = (const float*)d_in[6];
    const float* b3 = (const float*)d_in[7];
    float* out = (float*)d_out;
    (void)in_sizes; (void)n_in; (void)out_size;

    void *pF, *pA, *pB, *pa2, *ph12, *ph22, *pw1, *pw2, *pw3;
    cudaGetSymbolAddress(&pF,  g_bufF);
    cudaGetSymbolAddress(&pA,  g_bufA);
    cudaGetSymbolAddress(&pB,  g_bufB);
    cudaGetSymbolAddress(&pa2, g_a2y);
    cudaGetSymbolAddress(&ph12, g_h12);
    cudaGetSymbolAddress(&ph22, g_h22);
    cudaGetSymbolAddress(&pw1, g_wt1);
    cudaGetSymbolAddress(&pw2, g_wt2);
    cudaGetSymbolAddress(&pw3, g_wt3);
    float* bufF = (float*)pF;
    float* bufA = (float*)pA;
    float* bufB = (float*)pB;
    __nv_bfloat16* a2y = (__nv_bfloat16*)pa2;
    __nv_bfloat16* h12 = (__nv_bfloat16*)ph12;
    __nv_bfloat16* h22 = (__nv_bfloat16*)ph22;
    __nv_bfloat16* wt1 = (__nv_bfloat16*)pw1;
    __nv_bfloat16* wt2 = (__nv_bfloat16*)pw2;
    __nv_bfloat16* wt3 = (__nv_bfloat16*)pw3;

    // dynamic smem sizes (opt-in once per template; idempotent)
    const int smem12 = 2 * (128 * 80) + 2 * (256 * 80);   // 61440
    const int smem3a = 2 * (128 * 80) + 2 * (64 * 80);    // 30720
    const int smem3b = 128 * 66 * 4;                      // 33792 (logits stage)
    const int smem3  = (smem3a > smem3b) ? smem3a : smem3b;
    cudaFuncSetAttribute((const void*)mgemm_kernel<384, 256, 256, 512, 0>,
                         cudaFuncAttributeMaxDynamicSharedMemorySize, smem12);
    cudaFuncSetAttribute((const void*)mgemm_kernel<768, 512, 256, 512, 0>,
                         cudaFuncAttributeMaxDynamicSharedMemorySize, smem12);
    cudaFuncSetAttribute((const void*)mgemm_kernel<768, 512, 64, 256, 1>,
                         cudaFuncAttributeMaxDynamicSharedMemorySize, smem3);

    // 1) prep: zero cnt + init f (fused)
    prep_kernel<<<SCAN_BLOCKS + (int)INIT_BLOCKS, 256>>>(x);

    // 2) CSR build
    hist_kernel<<<(N_EDGES + 255) / 256, 256>>>(ei);
    scan1_kernel<<<SCAN_BLOCKS, 256>>>();
    scan3f_kernel<<<SCAN_BLOCKS, 256>>>();
    fill_kernel<<<(N_EDGES + 255) / 256, 256>>>(ei);

    // 3) weight conversions (fused)
    convw_all_kernel<<<(114688 + 255) / 256, 256>>>(W1, W2, W3);

    // 4) Horner propagation: t_k = f + A t_{k-1}; t0 = f
    const int spmm_blocks = (N_NODES * 32 + 255) / 256;
    spmm_kernel<false><<<spmm_blocks, 256>>>(bufF, bufA);
    spmm_kernel<false><<<spmm_blocks, 256>>>(bufA, bufB);
    spmm_kernel<false><<<spmm_blocks, 256>>>(bufB, bufA);
    spmm_kernel<false><<<spmm_blocks, 256>>>(bufA, bufB);
    spmm_kernel<true><<<spmm_blocks, 256>>>(bufB, bufA);

    // 5) MLP on tensor cores (bf16 3-term split, A stored [hi|lo]), single N pass
    const int mtiles = (N_NODES + 127) / 128;  // 391
    mgemm_kernel<384, 256, 256, 512, 0><<<mtiles, 512, smem12>>>(a2y, wt1, b1, nullptr, h12);
    mgemm_kernel<768, 512, 256, 512, 0><<<mtiles, 512, smem12>>>(h12, wt2, b2, nullptr, h22);
    mgemm_kernel<768, 512, 64, 256, 1><<<mtiles, 256, smem3>>>(h22, wt3, b3, out, nullptr);
}

// round 7
// speedup vs baseline: 1.6018x; 1.0083x over previous
#include <cuda_runtime.h>
#include <cuda_bf16.h>
#include <math.h>
#include <stdint.h>

#define N_NODES 50000
#define N_EDGES 500000
#define IN_C    128
#define HID_C   256
#define OUT_C   64
#define SCAN_BLOCKS ((N_NODES + 255) / 256)   // 196
#define INIT_BLOCKS (((size_t)N_NODES * IN_C / 4 + 255) / 256)  // 6250
#define SPMM_BLOCKS 1184                       // 148 SMs x 8 blocks, grid-stride
#define SPMM_WARPS  (SPMM_BLOCKS * 8)          // 9472

// ===================== scratch (static device globals) ======================
__device__ int   g_cnt[N_NODES];
__device__ int   g_rp [N_NODES];    // row start (order-free bucket allocation)
__device__ int   g_wp [N_NODES];    // fill cursor
__device__ int   g_ctr;
__device__ int   g_col[N_EDGES];
__device__ float g_bufF[(size_t)N_NODES * IN_C];   // f = x * 0.5
__device__ float g_bufA[(size_t)N_NODES * IN_C];   // Horner ping
__device__ float g_bufB[(size_t)N_NODES * IN_C];   // Horner pong
// bf16 split operands: A stored [hi | lo] (2K0 wide); W stored [hi | hi | lo] (3K0)
__device__ __nv_bfloat16 g_a2y [(size_t)N_NODES * (2 * IN_C)];   // 50000 x 256
__device__ __nv_bfloat16 g_h12 [(size_t)N_NODES * (2 * HID_C)];  // 50000 x 512
__device__ __nv_bfloat16 g_h22 [(size_t)N_NODES * (2 * HID_C)];  // 50000 x 512
__device__ __nv_bfloat16 g_wt1 [(size_t)HID_C * (3 * IN_C)];
__device__ __nv_bfloat16 g_wt2 [(size_t)HID_C * (3 * HID_C)];
__device__ __nv_bfloat16 g_wt3 [(size_t)OUT_C * (3 * HID_C)];

// ===================== small helpers ========================================
__device__ __forceinline__ uint32_t smem_u32(const void* p) {
    uint32_t a;
    asm("{ .reg .u64 t; cvta.to.shared.u64 t, %1; cvt.u32.u64 %0, t; }" : "=r"(a) : "l"(p));
    return a;
}
__device__ __forceinline__ uint32_t pack_hi2(float a, float b, float& la, float& lb) {
    __nv_bfloat16 ah = __float2bfloat16(a);
    __nv_bfloat16 bh = __float2bfloat16(b);
    la = a - __bfloat162float(ah);
    lb = b - __bfloat162float(bh);
    __nv_bfloat162 h2; h2.x = ah; h2.y = bh;
    return *(uint32_t*)&h2;
}
__device__ __forceinline__ uint32_t pack_bf2(float a, float b) {
    __nv_bfloat162 h2; h2.x = __float2bfloat16(a); h2.y = __float2bfloat16(b);
    return *(uint32_t*)&h2;
}
__device__ __forceinline__ void ldsm_x4(uint32_t (&r)[4], uint32_t addr) {
    asm volatile("ldmatrix.sync.aligned.m8n8.x4.shared.b16 {%0,%1,%2,%3},[%4];"
                 : "=r"(r[0]), "=r"(r[1]), "=r"(r[2]), "=r"(r[3]) : "r"(addr));
}
__device__ __forceinline__ void ldsm_x2(uint32_t (&r)[2], uint32_t addr) {
    asm volatile("ldmatrix.sync.aligned.m8n8.x2.shared.b16 {%0,%1},[%2];"
                 : "=r"(r[0]), "=r"(r[1]) : "r"(addr));
}
__device__ __forceinline__ void mma_bf16(float (&d)[4], const uint32_t (&a)[4],
                                         const uint32_t (&b)[2]) {
    asm volatile("mma.sync.aligned.m16n8k16.row.col.f32.bf16.bf16.f32 "
                 "{%0,%1,%2,%3},{%4,%5,%6,%7},{%8,%9},{%0,%1,%2,%3};"
                 : "+f"(d[0]), "+f"(d[1]), "+f"(d[2]), "+f"(d[3])
                 : "r"(a[0]), "r"(a[1]), "r"(a[2]), "r"(a[3]), "r"(b[0]), "r"(b[1]));
}
__device__ __forceinline__ void cp16(uint32_t dst, const void* src, int sz) {
    asm volatile("cp.async.cg.shared.global [%0],[%1],16,%2;"
                 :: "r"(dst), "l"(src), "r"(sz) : "memory");
}
__device__ __forceinline__ void cp16(uint32_t dst, const void* src) {
    asm volatile("cp.async.cg.shared.global [%0],[%1],16;"
                 :: "r"(dst), "l"(src) : "memory");
}
#define CP_COMMIT() asm volatile("cp.async.commit_group;" ::: "memory")
#define CP_WAIT0()  asm volatile("cp.async.wait_group 0;" ::: "memory")

// ===================== prep: zero cnt + ctr + init f ========================
__global__ void prep_kernel(const float* __restrict__ x) {
    int b = blockIdx.x;
    if (b == 0 && threadIdx.x == 0) g_ctr = 0;
    if (b < SCAN_BLOCKS) {
        int i = b * 256 + threadIdx.x;
        if (i < N_NODES) g_cnt[i] = 0;
    } else {
        size_t i = (size_t)(b - SCAN_BLOCKS) * 256 + threadIdx.x;
        size_t n4 = (size_t)N_NODES * IN_C / 4;
        if (i < n4) {
            float4 v = ((const float4*)x)[i];
            v.x *= 0.5f; v.y *= 0.5f; v.z *= 0.5f; v.w *= 0.5f;
            ((float4*)g_bufF)[i] = v;
        }
    }
}

// ===================== CSR build ============================================
__global__ void hist_kernel(const int* __restrict__ ei) {
    int e = blockIdx.x * blockDim.x + threadIdx.x;
    if (e < N_EDGES) atomicAdd(&g_cnt[ei[e]], 1);
}
// one-kernel bucket allocation: block-local scan + one global atomic per block.
// Buckets need not be in row order — any disjoint allocation is a valid CSR.
__global__ void scanA_kernel() {
    int b = blockIdx.x, t = threadIdx.x;
    int i = b * 256 + t;
    int lane = t & 31, w = t >> 5;
    int v = (i < N_NODES) ? g_cnt[i] : 0;
    int x = v;
#pragma unroll
    for (int o = 1; o < 32; o <<= 1) {
        int y = __shfl_up_sync(0xFFFFFFFFu, x, o);
        if (lane >= o) x += y;
    }
    __shared__ int ws[8];
    __shared__ int sbase;
    if (lane == 31) ws[w] = x;
    __syncthreads();
    if (w == 0 && lane < 8) {
        int y = ws[lane];
#pragma unroll
        for (int o = 1; o < 8; o <<= 1) {
            int z = __shfl_up_sync(0xFFu, y, o);
            if (lane >= o) y += z;
        }
        ws[lane] = y;
    }
    __syncthreads();
    int incl = x + (w > 0 ? ws[w - 1] : 0);
    if (t == 255) sbase = atomicAdd(&g_ctr, incl);  // incl@255 == block total
    __syncthreads();
    if (i < N_NODES) {
        int st = sbase + incl - v;
        g_rp[i] = st;
        g_wp[i] = st;
    }
}
__global__ void fill_kernel(const int* __restrict__ ei) {
    int e = blockIdx.x * blockDim.x + threadIdx.x;
    if (e < N_EDGES) {
        int s = ei[e];
        int d = ei[N_EDGES + e];
        int p = atomicAdd(&g_wp[s], 1);
        g_col[p] = d;
    }
}

// ===================== propagation ==========================================
// Horner hop: tout[r] = f[r] + sum_{j in adj(r)} tin[j]   (grid-stride warps)
// last hop (EMIT): emit bf16 [hi|lo] of tout/6 directly
template <bool EMIT>
__global__ void __launch_bounds__(256) spmm_kernel(const float* __restrict__ tin,
                                                   float* __restrict__ tout) {
    int w0 = (blockIdx.x * blockDim.x + threadIdx.x) >> 5;
    int lane = threadIdx.x & 31;
    for (int row = w0; row < N_NODES; row += SPMM_WARPS) {
        int s = g_rp[row];
        int e = s + g_cnt[row];
        float4 acc = *(const float4*)(g_bufF + (size_t)row * IN_C + lane * 4);
        int idx = s;
        for (; idx + 3 < e; idx += 4) {
            int j0 = g_col[idx];
            int j1 = g_col[idx + 1];
            int j2 = g_col[idx + 2];
            int j3 = g_col[idx + 3];
            float4 v0 = *(const float4*)(tin + (size_t)j0 * IN_C + lane * 4);
            float4 v1 = *(const float4*)(tin + (size_t)j1 * IN_C + lane * 4);
            float4 v2 = *(const float4*)(tin + (size_t)j2 * IN_C + lane * 4);
            float4 v3 = *(const float4*)(tin + (size_t)j3 * IN_C + lane * 4);
            acc.x += (v0.x + v1.x) + (v2.x + v3.x);
            acc.y += (v0.y + v1.y) + (v2.y + v3.y);
            acc.z += (v0.z + v1.z) + (v2.z + v3.z);
            acc.w += (v0.w + v1.w) + (v2.w + v3.w);
        }
        for (; idx < e; ++idx) {
            int j = g_col[idx];
            float4 v = *(const float4*)(tin + (size_t)j * IN_C + lane * 4);
            acc.x += v.x; acc.y += v.y; acc.z += v.z; acc.w += v.w;
        }
        if (!EMIT) {
            *(float4*)(tout + (size_t)row * IN_C + lane * 4) = acc;
        } else {
            const float sc = 1.0f / 6.0f;
            float a = acc.x * sc, b = acc.y * sc, c = acc.z * sc, d = acc.w * sc;
            float la, lb, lc, ld;
            uint2 h2, l2;
            h2.x = pack_hi2(a, b, la, lb);
            h2.y = pack_hi2(c, d, lc, ld);
            l2.x = pack_bf2(la, lb);
            l2.y = pack_bf2(lc, ld);
            __nv_bfloat16* orow = g_a2y + (size_t)row * (2 * IN_C);
            int c0 = lane * 4;
            *(uint2*)(orow + c0)        = h2;
            *(uint2*)(orow + IN_C + c0) = l2;
        }
    }
}

// ===================== fused weight conversion ==============================
__device__ __forceinline__ void conv_one(const float* __restrict__ W,
                                         __nv_bfloat16* __restrict__ Wt3,
                                         int K, int N, int i) {
    int k = i / N, n = i % N;
    float v = W[i];
    __nv_bfloat16 hi = __float2bfloat16(v);
    __nv_bfloat16 lo = __float2bfloat16(v - __bfloat162float(hi));
    size_t rb = (size_t)n * 3 * K;
    Wt3[rb + k]         = hi;
    Wt3[rb + K + k]     = hi;
    Wt3[rb + 2 * K + k] = lo;
}
__global__ void convw_all_kernel(const float* __restrict__ W1,
                                 const float* __restrict__ W2,
                                 const float* __restrict__ W3) {
    int i = blockIdx.x * blockDim.x + threadIdx.x;
    const int n1 = IN_C * HID_C;            // 32768
    const int n2 = n1 + HID_C * HID_C;      // 98304
    const int n3 = n2 + HID_C * OUT_C;      // 114688
    if (i < n1)      conv_one(W1, g_wt1, IN_C,  HID_C, i);
    else if (i < n2) conv_one(W2, g_wt2, HID_C, HID_C, i - n1);
    else if (i < n3) conv_one(W3, g_wt3, HID_C, OUT_C, i - n2);
}

// ===================== mma.sync GEMM ========================================
// CTA tile 128 x N_TILE (full N in one pass), BK=32; warp tile 32 x WTN.
// Logical K = LOGK (= 3*K0); A physically [hi|lo] width APHYS (= 2*K0):
//   kphys = kbase >= APHYS ? kbase - APHYS : kbase  (third block re-reads hi)
// W stored [hi|hi|lo] width LOGK.
// OUTMODE 0: relu(acc+bias) -> bf16 pair [hi|lo] in outb (row width 2*HID_C)
// OUTMODE 1: fused log-softmax(acc+bias) -> fp32 outf (row width 64)
template <int LOGK, int APHYS, int N_TILE, int THREADS, int OUTMODE>
__global__ void __launch_bounds__(THREADS, (THREADS == 512) ? 1 : 2) mgemm_kernel(
    const __nv_bfloat16* __restrict__ A2, const __nv_bfloat16* __restrict__ Bt3,
    const float* __restrict__ bias, float* __restrict__ outf,
    __nv_bfloat16* __restrict__ outb)
{
    constexpr int NK = LOGK / 32;
    constexpr int WARPS_N = THREADS / 128;
    constexpr int WTN = N_TILE / WARPS_N;
    constexpr int NI = WTN / 8;
    constexpr int AROWB = 80;
    constexpr int A_STRIDE = 128 * AROWB;
    constexpr int B_STRIDE = N_TILE * AROWB;

    extern __shared__ __align__(16) unsigned char smem[];
    __shared__ float sbias[N_TILE];

    unsigned char* smA = smem;
    unsigned char* smB = smem + 2 * A_STRIDE;

    const int t = threadIdx.x;
    const int lane = t & 31;
    const int wid = t >> 5;
    const int wm = wid & 3;
    const int wn = wid >> 2;
    const int m0 = blockIdx.x * 128;

    const uint32_t smA_addr = smem_u32(smA);
    const uint32_t smB_addr = smem_u32(smB);

    if (t < N_TILE) sbias[t] = bias[t];

    float acc[2][NI][4];
#pragma unroll
    for (int mi = 0; mi < 2; ++mi)
#pragma unroll
        for (int ni = 0; ni < NI; ++ni)
#pragma unroll
            for (int q = 0; q < 4; ++q) acc[mi][ni][q] = 0.f;

    auto load_tile = [&](int kbase, int s) {
        const int kphys = (kbase >= APHYS) ? (kbase - APHYS) : kbase;
#pragma unroll
        for (int u = t; u < 512; u += THREADS) {
            int row = u >> 2, seg = u & 3;
            uint32_t dst = smA_addr + s * A_STRIDE + row * AROWB + seg * 16;
            int m = m0 + row;
            int mc = (m < N_NODES) ? m : 0;
            const __nv_bfloat16* src = A2 + (size_t)mc * APHYS + kphys + seg * 8;
            cp16(dst, src, (m < N_NODES) ? 16 : 0);
        }
#pragma unroll
        for (int u = t; u < N_TILE * 4; u += THREADS) {
            int row = u >> 2, seg = u & 3;
            uint32_t dst = smB_addr + s * B_STRIDE + row * AROWB + seg * 16;
            const __nv_bfloat16* src = Bt3 + (size_t)row * LOGK + kbase + seg * 8;
            cp16(dst, src);
        }
    };

    load_tile(0, 0);
    CP_COMMIT();
    CP_WAIT0();
    __syncthreads();

    for (int kt = 0; kt < NK; ++kt) {
        const int s = kt & 1;
        if (kt + 1 < NK) { load_tile((kt + 1) * 32, s ^ 1); CP_COMMIT(); }

        const uint32_t abase0 = smA_addr + s * A_STRIDE +
                                (wm * 32 + (lane & 15)) * AROWB + ((lane >> 4) * 16);
        const uint32_t bbase0 = smB_addr + s * B_STRIDE +
                                (wn * WTN + (lane & 7)) * AROWB + (((lane >> 3) & 1) * 16);
#pragma unroll
        for (int h = 0; h < 2; ++h) {
            uint32_t aF[2][4];
            uint32_t bF[NI][2];
            ldsm_x4(aF[0], abase0 + h * 32);
            ldsm_x4(aF[1], abase0 + h * 32 + 16 * AROWB);
#pragma unroll
            for (int ni = 0; ni < NI; ++ni)
                ldsm_x2(bF[ni], bbase0 + h * 32 + ni * 8 * AROWB);
#pragma unroll
            for (int mi = 0; mi < 2; ++mi)
#pragma unroll
                for (int ni = 0; ni < NI; ++ni)
                    mma_bf16(acc[mi][ni], aF[mi], bF[ni]);
        }

        if (kt + 1 < NK) { CP_WAIT0(); __syncthreads(); }
    }

    // ---------------- epilogue ----------------
    const int lr = lane >> 2;
    const int lc = (lane & 3) * 2;
    if (OUTMODE == 0) {
#pragma unroll
        for (int mi = 0; mi < 2; ++mi) {
#pragma unroll
            for (int half = 0; half < 2; ++half) {
                const int m = m0 + wm * 32 + mi * 16 + lr + half * 8;
                if (m < N_NODES) {
                    __nv_bfloat16* orow = outb + (size_t)m * (2 * HID_C);
#pragma unroll
                    for (int ni = 0; ni < NI; ++ni) {
                        int cl = wn * WTN + ni * 8 + lc;
                        float a = acc[mi][ni][half * 2 + 0] + sbias[cl];
                        float b = acc[mi][ni][half * 2 + 1] + sbias[cl + 1];
                        a = fmaxf(a, 0.f); b = fmaxf(b, 0.f);
                        float la, lb;
                        uint32_t hi = pack_hi2(a, b, la, lb);
                        uint32_t lo = pack_bf2(la, lb);
                        *(uint32_t*)(orow + cl)         = hi;
                        *(uint32_t*)(orow + HID_C + cl) = lo;
                    }
                }
            }
        }
    } else {
        float* slog = (float*)smem;
        __syncthreads();
#pragma unroll
        for (int mi = 0; mi < 2; ++mi) {
#pragma unroll
            for (int half = 0; half < 2; ++half) {
                const int r = wm * 32 + mi * 16 + lr + half * 8;
#pragma unroll
                for (int ni = 0; ni < NI; ++ni) {
                    int cl = wn * WTN + ni * 8 + lc;
                    float a = acc[mi][ni][half * 2 + 0] + sbias[cl];
                    float b = acc[mi][ni][half * 2 + 1] + sbias[cl + 1];
                    *(float2*)(slog + r * 66 + cl) = make_float2(a, b);
                }
            }
        }
        __syncthreads();
#pragma unroll
        for (int rr = 0; rr < 16; ++rr) {
            int r = wid * 16 + rr;
            int m = m0 + r;
            float v0 = slog[r * 66 + lane];
            float v1 = slog[r * 66 + lane + 32];
            float mx = fmaxf(v0, v1);
#pragma unroll
            for (int off = 16; off > 0; off >>= 1)
                mx = fmaxf(mx, __shfl_xor_sync(0xFFFFFFFFu, mx, off));
            float sm = expf(v0 - mx) + expf(v1 - mx);
#pragma unroll
            for (int off = 16; off > 0; off >>= 1)
                sm += __shfl_xor_sync(0xFFFFFFFFu, sm, off);
            float l = mx + logf(sm);
            if (m < N_NODES) {
                outf[(size_t)m * 64 + lane]      = v0 - l;
                outf[(size_t)m * 64 + lane + 32] = v1 - l;
            }
        }
    }
}

// ===================== launch ===============================================
extern "C" void kernel_launch(void* const* d_in, const int* in_sizes, int n_in,
                              void* d_out, int out_size) {
    const float* x  = (const float*)d_in[0];
    const int*   ei = (const int*)  d_in[1];
    const float* W1 = (const float*)d_in[2];
    const float* b1 = (const float*)d_in[3];
    const float* W2 = (const float*)d_in[4];
    const float* b2 = (const float*)d_in[5];
    const float* W3 = (const float*)d_in[6];
    const float* b3 = (const float*)d_in[7];
    float* out = (float*)d_out;
    (void)in_sizes; (void)n_in; (void)out_size;

    void *pF, *pA, *pB, *pa2, *ph12, *ph22, *pw1, *pw2, *pw3;
    cudaGetSymbolAddress(&pF,  g_bufF);
    cudaGetSymbolAddress(&pA,  g_bufA);
    cudaGetSymbolAddress(&pB,  g_bufB);
    cudaGetSymbolAddress(&pa2, g_a2y);
    cudaGetSymbolAddress(&ph12, g_h12);
    cudaGetSymbolAddress(&ph22, g_h22);
    cudaGetSymbolAddress(&pw1, g_wt1);
    cudaGetSymbolAddress(&pw2, g_wt2);
    cudaGetSymbolAddress(&pw3, g_wt3);
    float* bufF = (float*)pF;
    float* bufA = (float*)pA;
    float* bufB = (float*)pB;
    __nv_bfloat16* a2y = (__nv_bfloat16*)pa2;
    __nv_bfloat16* h12 = (__nv_bfloat16*)ph12;
    __nv_bfloat16* h22 = (__nv_bfloat16*)ph22;
    __nv_bfloat16* wt1 = (__nv_bfloat16*)pw1;
    __nv_bfloat16* wt2 = (__nv_bfloat16*)pw2;
    __nv_bfloat16* wt3 = (__nv_bfloat16*)pw3;

    const int smem12 = 2 * (128 * 80) + 2 * (256 * 80);   // 61440
    const int smem3a = 2 * (128 * 80) + 2 * (64 * 80);    // 30720
    const int smem3b = 128 * 66 * 4;                      // 33792
    const int smem3  = (smem3a > smem3b) ? smem3a : smem3b;
    cudaFuncSetAttribute((const void*)mgemm_kernel<384, 256, 256, 512, 0>,
                         cudaFuncAttributeMaxDynamicSharedMemorySize, smem12);
    cudaFuncSetAttribute((const void*)mgemm_kernel<768, 512, 256, 512, 0>,
                         cudaFuncAttributeMaxDynamicSharedMemorySize, smem12);
    cudaFuncSetAttribute((const void*)mgemm_kernel<768, 512, 64, 256, 1>,
                         cudaFuncAttributeMaxDynamicSharedMemorySize, smem3);

    // launches 0..4: prep, hist, scanA, fill, spmm1  -> ncu (-s 5) captures spmm2
    prep_kernel<<<SCAN_BLOCKS + (int)INIT_BLOCKS, 256>>>(x);
    hist_kernel<<<(N_EDGES + 255) / 256, 256>>>(ei);
    scanA_kernel<<<SCAN_BLOCKS, 256>>>();
    fill_kernel<<<(N_EDGES + 255) / 256, 256>>>(ei);

    // Horner propagation: t_k = f + A t_{k-1}; t0 = f
    spmm_kernel<false><<<SPMM_BLOCKS, 256>>>(bufF, bufA);
    spmm_kernel<false><<<SPMM_BLOCKS, 256>>>(bufA, bufB);   // <- profiled
    spmm_kernel<false><<<SPMM_BLOCKS, 256>>>(bufB, bufA);
    spmm_kernel<false><<<SPMM_BLOCKS, 256>>>(bufA, bufB);
    spmm_kernel<true><<<SPMM_BLOCKS, 256>>>(bufB, bufA);

    // weight conversion (only needed before gemm1)
    convw_all_kernel<<<(114688 + 255) / 256, 256>>>(W1, W2, W3);

    // MLP on tensor cores (bf16 3-term split, A stored [hi|lo]), single N pass
    const int mtiles = (N_NODES + 127) / 128;  // 391
    mgemm_kernel<384, 256, 256, 512, 0><<<mtiles, 512, smem12>>>(a2y, wt1, b1, nullptr, h12);
    mgemm_kernel<768, 512, 256, 512, 0><<<mtiles, 512, smem12>>>(h12, wt2, b2, nullptr, h22);
    mgemm_kernel<768, 512, 64, 256, 1><<<mtiles, 256, smem3>>>(h22, wt3, b3, out, nullptr);
}